// round 11
// baseline (speedup 1.0000x reference)
#include <cuda_runtime.h>
#include <math.h>

#define NSTACK 4
#define BATCH  4
#define LSEQ   600
#define DMODEL 36
#define DFF    144
#define QT     30
#define NTILES 20
#define NI     19
#define KVP    37   // padded K/V row stride in smem (conflict-free)

// ---------------- scratch ----------------
__device__ float g_z[NSTACK*BATCH*LSEQ*DMODEL];
__device__ float g_q[NSTACK*BATCH*LSEQ*DMODEL];
__device__ float g_k[NSTACK*BATCH*LSEQ*DMODEL];
__device__ float g_v[NSTACK*BATCH*LSEQ*DMODEL];
__device__ float g_o[NSTACK*BATCH*LSEQ*DMODEL];
__device__ float g_gate[NSTACK*BATCH*DMODEL];

__device__ __forceinline__ int pick4(int4 v, int s) {
    return (s == 0) ? v.x : (s == 1) ? v.y : (s == 2) ? v.z : v.w;
}
__device__ __forceinline__ float wred(float v) {
#pragma unroll
    for (int o = 16; o > 0; o >>= 1) v += __shfl_xor_sync(0xffffffffu, v, o);
    return v;
}
__device__ __forceinline__ float ex2(float x) {
    float r;
    asm("ex2.approx.f32 %0, %1;" : "=f"(r) : "f"(x));
    return r;
}
// gelu(tanh approx) = u * sigmoid(2 * 0.79788456*(u + 0.044715 u^3))
__device__ __forceinline__ float gelu(float u) {
    float a = 1.5957691216057308f * (u + 0.044715f * u * u * u);
    return __fdividef(u, 1.f + __expf(-a));
}
__device__ __forceinline__ void cp4(float* dst, const float* __restrict__ src,
                                    int n, int tid, int nt) {
    const float4* s4 = (const float4*)src;
    float4* d4 = (float4*)dst;
    for (int i = tid; i < (n >> 2); i += nt) d4[i] = s4[i];
}

// ---------------- embedding ----------------
__global__ void embed_kernel(const float* __restrict__ x)
{
    int idx = blockIdx.x * blockDim.x + threadIdx.x;
    if (idx >= NSTACK * BATCH * LSEQ * DMODEL) return;
    int d = idx % 36;
    int l = (idx / 36) % 600;
    int b = (idx / 21600) % 4;
    int j = d >> 1;
    float freq = __expf(-logf(10000.f) * (float)(2 * j) / 36.f);
    float ang = (float)l * freq;
    float pe = (d & 1) ? cosf(ang) : sinf(ang);
    g_z[idx] = x[b * 21600 + d * 600 + l] + pe;
}

// =============================================================
// Initial LN1 + QKV: 512 threads, 16 warps, 2 rows/warp (R10)
// =============================================================
#define LQ_WQ 0
#define LQ_WK 1296
#define LQ_WV 2592
#define LQ_LG 3888
#define LQ_LB 3924
#define LQ_BQ 3960
#define LQ_BK 3996
#define LQ_BV 4032
#define LQ_YB 4068
#define LQ_TOT (4068 + 32*40)

__global__ void __launch_bounds__(512, 2) lnqkv2_kernel(
    int4 layer4,
    const float* __restrict__ ln1_g, const float* __restrict__ ln1_b,
    const float* __restrict__ Wq, const float* __restrict__ bq,
    const float* __restrict__ Wk, const float* __restrict__ bk,
    const float* __restrict__ Wv, const float* __restrict__ bv)
{
    extern __shared__ float sm[];
    int tid = threadIdx.x, lane = tid & 31, w = tid >> 5;
    int s = blockIdx.z;
    int L = pick4(layer4, s);

    cp4(sm + LQ_WQ, Wq + L * 1296, 1296, tid, 512);
    cp4(sm + LQ_WK, Wk + L * 1296, 1296, tid, 512);
    cp4(sm + LQ_WV, Wv + L * 1296, 1296, tid, 512);
    cp4(sm + LQ_LG, ln1_g + L * 36, 36, tid, 512);
    cp4(sm + LQ_LB, ln1_b + L * 36, 36, tid, 512);
    cp4(sm + LQ_BQ, bq + L * 36, 36, tid, 512);
    cp4(sm + LQ_BK, bk + L * 36, 36, tid, 512);
    cp4(sm + LQ_BV, bv + L * 36, 36, tid, 512);
    __syncthreads();

    int rA = blockIdx.x * 32 + w * 2;
    int gA = s * 2400 + rA, gB = gA + 1;
    int j = lane, j2 = lane + 32;
    bool e2 = lane < 4;
    float* bufA = sm + LQ_YB + (w * 2) * 40;
    float* bufB = bufA + 40;

    bufA[lane] = g_z[gA * 36 + lane];
    bufB[lane] = g_z[gB * 36 + lane];
    if (e2) { bufA[j2] = g_z[gA * 36 + j2]; bufB[j2] = g_z[gB * 36 + j2]; }
    __syncwarp();

    float tA0 = bufA[j], tB0 = bufB[j];
    float tA1 = e2 ? bufA[j2] : 0.f, tB1 = e2 ? bufB[j2] : 0.f;
    float sA = wred(tA0 + (e2 ? tA1 : 0.f));
    float qA = wred(tA0 * tA0 + (e2 ? tA1 * tA1 : 0.f));
    float sB = wred(tB0 + (e2 ? tB1 : 0.f));
    float qB = wred(tB0 * tB0 + (e2 ? tB1 * tB1 : 0.f));
    float mA = sA * (1.f / 36.f), mB = sB * (1.f / 36.f);
    float rsA = rsqrtf(qA * (1.f / 36.f) - mA * mA + 1e-6f);
    float rsB = rsqrtf(qB * (1.f / 36.f) - mB * mB + 1e-6f);

    bufA[j] = sm[LQ_LG + j] * (tA0 - mA) * rsA + sm[LQ_LB + j];
    bufB[j] = sm[LQ_LG + j] * (tB0 - mB) * rsB + sm[LQ_LB + j];
    if (e2) {
        bufA[j2] = sm[LQ_LG + j2] * (tA1 - mA) * rsA + sm[LQ_LB + j2];
        bufB[j2] = sm[LQ_LG + j2] * (tB1 - mB) * rsB + sm[LQ_LB + j2];
    }
    __syncwarp();

    float qA0 = sm[LQ_BQ + j], qB0 = qA0;
    float kA0 = sm[LQ_BK + j], kB0 = kA0;
    float vA0 = sm[LQ_BV + j], vB0 = vA0;
    float qA1 = 0.f, qB1 = 0.f, kA1 = 0.f, kB1 = 0.f, vA1 = 0.f, vB1 = 0.f;
    if (e2) {
        qA1 = sm[LQ_BQ + j2]; qB1 = qA1;
        kA1 = sm[LQ_BK + j2]; kB1 = kA1;
        vA1 = sm[LQ_BV + j2]; vB1 = vA1;
    }
#pragma unroll
    for (int d = 0; d < 36; d++) {
        float av = bufA[d], bvv = bufB[d];
        float wq = sm[LQ_WQ + d * 36 + j];
        float wk = sm[LQ_WK + d * 36 + j];
        float wv = sm[LQ_WV + d * 36 + j];
        qA0 = fmaf(av, wq, qA0); qB0 = fmaf(bvv, wq, qB0);
        kA0 = fmaf(av, wk, kA0); kB0 = fmaf(bvv, wk, kB0);
        vA0 = fmaf(av, wv, vA0); vB0 = fmaf(bvv, wv, vB0);
        if (e2) {
            float wq2 = sm[LQ_WQ + d * 36 + j2];
            float wk2 = sm[LQ_WK + d * 36 + j2];
            float wv2 = sm[LQ_WV + d * 36 + j2];
            qA1 = fmaf(av, wq2, qA1); qB1 = fmaf(bvv, wq2, qB1);
            kA1 = fmaf(av, wk2, kA1); kB1 = fmaf(bvv, wk2, kB1);
            vA1 = fmaf(av, wv2, vA1); vB1 = fmaf(bvv, wv2, vB1);
        }
    }
    g_q[gA * 36 + j] = qA0; g_q[gB * 36 + j] = qB0;
    g_k[gA * 36 + j] = kA0; g_k[gB * 36 + j] = kB0;
    g_v[gA * 36 + j] = vA0; g_v[gB * 36 + j] = vB0;
    if (e2) {
        g_q[gA * 36 + j2] = qA1; g_q[gB * 36 + j2] = qB1;
        g_k[gA * 36 + j2] = kA1; g_k[gB * 36 + j2] = kB1;
        g_v[gA * 36 + j2] = vA1; g_v[gB * 36 + j2] = vB1;
    }
}

// =============================================================
// rowchain v2: row-per-lane GEMM tiling.
// 256 threads = 8 warps; block owns 64 rows (2 per lane).
// Weights broadcast from smem; acts conflict-free strided.
// Two-phase weight staging keeps smem at 95KB -> 2 blocks/SM.
// =============================================================
#define R2_WS    0
#define R2_BO    9072
#define R2_L2G   9108
#define R2_L2B   9144
#define R2_B1    9180
#define R2_B2    9324
#define R2_L1G   9360
#define R2_L1B   9396
#define R2_BQ3   9432
#define R2_BT    9540
#define R2_BY    (9540 + 64*37)
#define R2_BG    (9540 + 2*64*37)
#define R2_TOT   (9540 + 2*64*37 + 64*149)   // 23812 floats = 95.2 KB

__global__ void __launch_bounds__(256, 2) rowchain2_kernel(
    int4 layer4, int4 next4,
    const float* __restrict__ Wo, const float* __restrict__ bo,
    const float* __restrict__ ln2_g, const float* __restrict__ ln2_b,
    const float* __restrict__ W1, const float* __restrict__ b1,
    const float* __restrict__ W2, const float* __restrict__ b2,
    const float* __restrict__ ln1_g, const float* __restrict__ ln1_b,
    const float* __restrict__ Wq, const float* __restrict__ bq,
    const float* __restrict__ Wk, const float* __restrict__ bk,
    const float* __restrict__ Wv, const float* __restrict__ bv)
{
    extern __shared__ float sm[];
    int tid = threadIdx.x, lane = tid & 31, w = tid >> 5;
    int s = blockIdx.z;
    int L = pick4(layer4, s), Ln = pick4(next4, s);
    int sbase = s * 2400;
    int r0l = blockIdx.x * 64 + lane;   // stack-local row (always < 2400)
    int r1l = r0l + 32;
    bool v1 = (r1l < 2400);
    int g0 = sbase + r0l;
    int g1 = sbase + (v1 ? r1l : 2399);
    int lr0 = lane, lr1 = lane + 32;

    // ---- stage phase A: WO, W1, biases; o -> BUFY ----
    cp4(sm + R2_WS, Wo + L * 1296, 1296, tid, 256);
    cp4(sm + R2_WS + 1296, W1 + L * 5184, 5184, tid, 256);
    cp4(sm + R2_BO,  bo + L * 36, 36, tid, 256);
    cp4(sm + R2_L2G, ln2_g + L * 36, 36, tid, 256);
    cp4(sm + R2_L2B, ln2_b + L * 36, 36, tid, 256);
    cp4(sm + R2_B1,  b1 + L * 144, 144, tid, 256);
    cp4(sm + R2_B2,  b2 + L * 36, 36, tid, 256);
    if (Ln >= 0) {
        cp4(sm + R2_L1G, ln1_g + Ln * 36, 36, tid, 256);
        cp4(sm + R2_L1B, ln1_b + Ln * 36, 36, tid, 256);
        cp4(sm + R2_BQ3,      bq + Ln * 36, 36, tid, 256);
        cp4(sm + R2_BQ3 + 36, bk + Ln * 36, 36, tid, 256);
        cp4(sm + R2_BQ3 + 72, bv + Ln * 36, 36, tid, 256);
    }
    {
        int rowcap = 2399 - blockIdx.x * 64;   // max valid local row
        for (int i = tid; i < 64 * 36; i += 256) {
            int lr = i / 36, c = i - lr * 36;
            int lrc = lr < rowcap ? lr : rowcap;
            sm[R2_BY + lr * 37 + c] = g_o[(sbase + blockIdx.x * 64 + lrc) * 36 + c];
        }
    }
    __syncthreads();

    int ob = (w < 6) ? 5 * w : (w == 6 ? 30 : 31);   // cols ob..ob+4, overlap benign

    // ---- o-projection + residual -> t (regs) + BUFT ----
    float t0[5], t1[5];
#pragma unroll
    for (int k = 0; k < 5; k++) { t0[k] = sm[R2_BO + ob + k]; t1[k] = t0[k]; }
#pragma unroll
    for (int d = 0; d < 36; d++) {
        float a0 = sm[R2_BY + lr0 * 37 + d];
        float a1 = sm[R2_BY + lr1 * 37 + d];
#pragma unroll
        for (int k = 0; k < 5; k++) {
            float wv = sm[R2_WS + d * 36 + ob + k];
            t0[k] = fmaf(a0, wv, t0[k]);
            t1[k] = fmaf(a1, wv, t1[k]);
        }
    }
#pragma unroll
    for (int k = 0; k < 5; k++) {
        int c = ob + k;
        t0[k] += g_z[g0 * 36 + c];
        t1[k] += g_z[g1 * 36 + c];
        sm[R2_BT + lr0 * 37 + c] = t0[k];
        sm[R2_BT + lr1 * 37 + c] = t1[k];
    }
    __syncthreads();

    // ---- LN2 (per-lane full-row stats) -> y into BUFY ----
    float m0, rs0, m1, rs1;
    {
        float s0 = 0.f, q0 = 0.f, s1 = 0.f, q1 = 0.f;
#pragma unroll
        for (int d = 0; d < 36; d++) {
            float x0 = sm[R2_BT + lr0 * 37 + d];
            float x1 = sm[R2_BT + lr1 * 37 + d];
            s0 += x0; q0 = fmaf(x0, x0, q0);
            s1 += x1; q1 = fmaf(x1, x1, q1);
        }
        m0 = s0 * (1.f / 36.f); rs0 = rsqrtf(q0 * (1.f / 36.f) - m0 * m0 + 1e-6f);
        m1 = s1 * (1.f / 36.f); rs1 = rsqrtf(q1 * (1.f / 36.f) - m1 * m1 + 1e-6f);
    }
#pragma unroll
    for (int k = 0; k < 5; k++) {
        int c = ob + k;
        sm[R2_BY + lr0 * 37 + c] = sm[R2_L2G + c] * (t0[k] - m0) * rs0 + sm[R2_L2B + c];
        sm[R2_BY + lr1 * 37 + c] = sm[R2_L2G + c] * (t1[k] - m1) * rs1 + sm[R2_L2B + c];
    }
    __syncthreads();

    // ---- FFN1 + GELU -> BUFG ----
    {
        int cb = w * 18;
        float f0[18], f1[18];
#pragma unroll
        for (int k = 0; k < 18; k++) { f0[k] = sm[R2_B1 + cb + k]; f1[k] = f0[k]; }
#pragma unroll
        for (int d = 0; d < 36; d++) {
            float a0 = sm[R2_BY + lr0 * 37 + d];
            float a1 = sm[R2_BY + lr1 * 37 + d];
#pragma unroll
            for (int k = 0; k < 18; k++) {
                float wv = sm[R2_WS + 1296 + d * 144 + cb + k];
                f0[k] = fmaf(a0, wv, f0[k]);
                f1[k] = fmaf(a1, wv, f1[k]);
            }
        }
#pragma unroll
        for (int k = 0; k < 18; k++) {
            sm[R2_BG + lr0 * 149 + cb + k] = gelu(f0[k]);
            sm[R2_BG + lr1 * 149 + cb + k] = gelu(f1[k]);
        }
    }
    __syncthreads();

    // ---- stage phase B: W2, fused WQKV (overwrite WS) ----
    cp4(sm + R2_WS, W2 + L * 5184, 5184, tid, 256);
    if (Ln >= 0) {
        const float* Wm0 = Wq + Ln * 1296;
        const float* Wm1 = Wk + Ln * 1296;
        const float* Wm2 = Wv + Ln * 1296;
        for (int i = tid; i < 1296; i += 256) {
            int d = i / 36, c = i - d * 36;
            sm[R2_WS + 5184 + d * 108 + c]      = Wm0[i];
            sm[R2_WS + 5184 + d * 108 + 36 + c] = Wm1[i];
            sm[R2_WS + 5184 + d * 108 + 72 + c] = Wm2[i];
        }
    }
    __syncthreads();

    // ---- FFN2 + residual -> z (regs) + g_z + BUFT(in place) ----
    float z0[5], z1[5];
#pragma unroll
    for (int k = 0; k < 5; k++) { z0[k] = sm[R2_B2 + ob + k]; z1[k] = z0[k]; }
#pragma unroll 8
    for (int d = 0; d < 144; d++) {
        float a0 = sm[R2_BG + lr0 * 149 + d];
        float a1 = sm[R2_BG + lr1 * 149 + d];
#pragma unroll
        for (int k = 0; k < 5; k++) {
            float wv = sm[R2_WS + d * 36 + ob + k];
            z0[k] = fmaf(a0, wv, z0[k]);
            z1[k] = fmaf(a1, wv, z1[k]);
        }
    }
#pragma unroll
    for (int k = 0; k < 5; k++) {
        int c = ob + k;
        z0[k] += t0[k]; z1[k] += t1[k];
        g_z[g0 * 36 + c] = z0[k];
        if (v1) g_z[g1 * 36 + c] = z1[k];
        sm[R2_BT + lr0 * 37 + c] = z0[k];
        sm[R2_BT + lr1 * 37 + c] = z1[k];
    }
    __syncthreads();
    if (Ln < 0) return;

    // ---- LN1 (next layer) -> y into BUFY ----
    {
        float s0 = 0.f, q0 = 0.f, s1 = 0.f, q1 = 0.f;
#pragma unroll
        for (int d = 0; d < 36; d++) {
            float x0 = sm[R2_BT + lr0 * 37 + d];
            float x1 = sm[R2_BT + lr1 * 37 + d];
            s0 += x0; q0 = fmaf(x0, x0, q0);
            s1 += x1; q1 = fmaf(x1, x1, q1);
        }
        m0 = s0 * (1.f / 36.f); rs0 = rsqrtf(q0 * (1.f / 36.f) - m0 * m0 + 1e-6f);
        m1 = s1 * (1.f / 36.f); rs1 = rsqrtf(q1 * (1.f / 36.f) - m1 * m1 + 1e-6f);
    }
#pragma unroll
    for (int k = 0; k < 5; k++) {
        int c = ob + k;
        sm[R2_BY + lr0 * 37 + c] = sm[R2_L1G + c] * (z0[k] - m0) * rs0 + sm[R2_L1B + c];
        sm[R2_BY + lr1 * 37 + c] = sm[R2_L1G + c] * (z1[k] - m1) * rs1 + sm[R2_L1B + c];
    }
    __syncthreads();

    // ---- fused QKV (next layer) ----
    {
        int qb = (w < 7) ? 14 * w : 94;   // cols qb..qb+13 over 108, overlap benign
        float acc0[14], acc1[14];
#pragma unroll
        for (int k = 0; k < 14; k++) { acc0[k] = sm[R2_BQ3 + qb + k]; acc1[k] = acc0[k]; }
#pragma unroll
        for (int d = 0; d < 36; d++) {
            float a0 = sm[R2_BY + lr0 * 37 + d];
            float a1 = sm[R2_BY + lr1 * 37 + d];
#pragma unroll
            for (int k = 0; k < 14; k++) {
                float wv = sm[R2_WS + 5184 + d * 108 + qb + k];
                acc0[k] = fmaf(a0, wv, acc0[k]);
                acc1[k] = fmaf(a1, wv, acc1[k]);
            }
        }
#pragma unroll
        for (int k = 0; k < 14; k++) {
            int c = qb + k;
            float* dst = (c < 36) ? g_q : (c < 72) ? g_k : g_v;
            int col = (c < 36) ? c : (c < 72) ? c - 36 : c - 72;
            dst[g0 * 36 + col] = acc0[k];
            if (v1) dst[g1 * 36 + col] = acc1[k];
        }
    }
}

// =============================================================
// attention (R10, unchanged): padded smem, online softmax, ex2
// =============================================================
template<int DK, int NQ>
__device__ __forceinline__ void attn_head_group(
    const float* __restrict__ ksh, const float* __restrict__ vsh,
    const float* __restrict__ qsh, float* __restrict__ ob,
    int q0, int g, int off, int lane)
{
    float qreg[NQ][DK];
#pragma unroll
    for (int qq = 0; qq < NQ; qq++) {
        int ql = g * NQ + qq;
#pragma unroll
        for (int d = 0; d < DK; d++)
            qreg[qq][d] = (ql < QT) ? qsh[ql * 36 + off + d] : 0.f;
    }
    float acc[NQ][DK];
    float ssum[NQ];
#pragma unroll
    for (int qq = 0; qq < NQ; qq++) {
        ssum[qq] = 0.f;
#pragma unroll
        for (int d = 0; d < DK; d++) acc[qq][d] = 0.f;
    }
    const float scale2 = rsqrtf((float)DK) * 1.44269504088896f;
    for (int i = 0; i < NI; i++) {
        int m = i * 32 + lane;
        if (m < LSEQ) {
            const float* kr = ksh + m * KVP + off;
            const float* vr = vsh + m * KVP + off;
            float p[NQ];
#pragma unroll
            for (int qq = 0; qq < NQ; qq++) p[qq] = 0.f;
#pragma unroll
            for (int d = 0; d < DK; d++) {
                float kv = kr[d];
#pragma unroll
                for (int qq = 0; qq < NQ; qq++)
                    p[qq] = fmaf(qreg[qq][d], kv, p[qq]);
            }
#pragma unroll
            for (int qq = 0; qq < NQ; qq++) {
                p[qq] = ex2(p[qq] * scale2);
                ssum[qq] += p[qq];
            }
#pragma unroll
            for (int d = 0; d < DK; d++) {
                float vv = vr[d];
#pragma unroll
                for (int qq = 0; qq < NQ; qq++)
                    acc[qq][d] = fmaf(p[qq], vv, acc[qq][d]);
            }
        }
    }
    float inv[NQ];
#pragma unroll
    for (int qq = 0; qq < NQ; qq++) {
        float sv = wred(ssum[qq]);
        inv[qq] = 1.f / sv;
    }
#pragma unroll
    for (int qq = 0; qq < NQ; qq++) {
        int ql = g * NQ + qq;
#pragma unroll
        for (int d = 0; d < DK; d++) {
            float a = wred(acc[qq][d]);
            if (ql < QT && lane == ((qq * DK + d) & 31))
                ob[(q0 + ql) * 36 + off + d] = a * inv[qq];
        }
    }
}

template<int DK, int NQ>
__device__ void attn_run(const float* ksh, const float* vsh, const float* qsh,
                         float* ob, int q0, int lane, int wid)
{
    constexpr int H  = 36 / DK;
    constexpr int NG = (QT + NQ - 1) / NQ;
    for (int u = wid; u < H * NG; u += 16) {
        int hh = u / NG, g = u % NG;
        attn_head_group<DK, NQ>(ksh, vsh, qsh, ob, q0, g, hh * DK, lane);
    }
}

__global__ void __launch_bounds__(512, 1) attn_kernel(int4 heads4)
{
    extern __shared__ float sh[];
    float* ksh = sh;
    float* vsh = sh + 600 * KVP;
    float* qsh = sh + 1200 * KVP;
    int tile = blockIdx.x, b = blockIdx.y, s = blockIdx.z;
    int h = pick4(heads4, s);
    int base = (s * 4 + b) * 21600;

    const float4* kg = (const float4*)(g_k + base);
    const float4* vg = (const float4*)(g_v + base);
    for (int i4 = threadIdx.x; i4 < 5400; i4 += 512) {
        int row = i4 / 9, c = (i4 % 9) * 4;
        float4 kv = kg[i4], vv = vg[i4];
        float* kd = ksh + row * KVP + c;
        kd[0] = kv.x; kd[1] = kv.y; kd[2] = kv.z; kd[3] = kv.w;
        float* vd = vsh + row * KVP + c;
        vd[0] = vv.x; vd[1] = vv.y; vd[2] = vv.z; vd[3] = vv.w;
    }
    int q0 = tile * QT;
    for (int i = threadIdx.x; i < QT * 36; i += 512) qsh[i] = g_q[base + q0 * 36 + i];
    __syncthreads();

    int lane = threadIdx.x & 31, wid = threadIdx.x >> 5;
    float* ob = g_o + base;
    switch (h) {
        case 1:  attn_run<36, 1>(ksh, vsh, qsh, ob, q0, lane, wid); break;
        case 2:  attn_run<18, 2>(ksh, vsh, qsh, ob, q0, lane, wid); break;
        case 3:  attn_run<12, 3>(ksh, vsh, qsh, ob, q0, lane, wid); break;
        case 4:  attn_run<9,  4>(ksh, vsh, qsh, ob, q0, lane, wid); break;
        case 6:  attn_run<6,  6>(ksh, vsh, qsh, ob, q0, lane, wid); break;
        case 9:  attn_run<4,  6>(ksh, vsh, qsh, ob, q0, lane, wid); break;
        case 12: attn_run<3,  6>(ksh, vsh, qsh, ob, q0, lane, wid); break;
        case 18: attn_run<2,  6>(ksh, vsh, qsh, ob, q0, lane, wid); break;
        case 36: attn_run<1, 10>(ksh, vsh, qsh, ob, q0, lane, wid); break;
    }
}

// ---------------- SE gate ----------------
__global__ void __launch_bounds__(288) gate_kernel()
{
    int sb = blockIdx.x;
    __shared__ float red[288];
    int t = threadIdx.x;
    int c = t / 8, k = t % 8;
    float sum = 0.f;
    const float* zz = g_z + sb * 21600;
    for (int l = k; l < 600; l += 8) sum += zz[l * 36 + c];
    red[t] = sum;
    __syncthreads();
    if (k == 0) {
        float tot = 0.f;
#pragma unroll
        for (int i = 0; i < 8; i++) tot += red[c * 8 + i];
        float mean = tot * (1.f / 600.f);
        g_gate[sb * 36 + c] = 1.f / (1.f + __expf(-mean));
    }
}

// ---------------- conv + BN + ReLU ----------------
__global__ void __launch_bounds__(360) conv_kernel(
    const float* __restrict__ conv_w, const float* __restrict__ conv_b,
    const float* __restrict__ bn_g, const float* __restrict__ bn_b,
    const float* __restrict__ bn_mean, const float* __restrict__ bn_var,
    float* __restrict__ out)
{
    extern __shared__ float esh[];
    float* xf  = esh;
    float* wsh = esh + 144 * 32;
    int b = blockIdx.y, lbase = blockIdx.x * 30;
    int t = threadIdx.x;

    for (int idx = t; idx < 144 * 32; idx += 360) {
        int i = idx >> 5, lc = idx & 31;
        int l = lbase + lc - 1;
        float val = 0.f;
        if (l >= 0 && l < 600) {
            int s = i / 36, c = i % 36;
            val = g_gate[(s * 4 + b) * 36 + c] * g_z[((s * 4 + b) * 600 + l) * 36 + c];
        }
        xf[i * 32 + lc] = val;
    }
    for (int idx = t; idx < 36 * 432; idx += 360) {
        int o = idx / 432, rest = idx % 432;
        wsh[o * 433 + rest] = conv_w[idx];
    }
    __syncthreads();

    int o = t % 36, lj = t / 36;
    float scale = bn_g[o] * rsqrtf(bn_var[o] + 1e-5f);
    float shift = bn_b[o] - scale * bn_mean[o];
    float cb = conv_b[o];
    const float* w = wsh + o * 433;
#pragma unroll
    for (int rep = 0; rep < 3; rep++) {
        int lc = lj + rep * 10;
        float acc = cb;
#pragma unroll 8
        for (int i = 0; i < 144; i++) {
            float x0 = xf[i * 32 + lc];
            float x1 = xf[i * 32 + lc + 1];
            float x2 = xf[i * 32 + lc + 2];
            acc += x0 * w[i * 3 + 0] + x1 * w[i * 3 + 1] + x2 * w[i * 3 + 2];
        }
        float y = scale * acc + shift;
        out[b * 21600 + o * 600 + lbase + lc] = fmaxf(y, 0.f);
    }
}

// ---------------- host driver ----------------
extern "C" void kernel_launch(void* const* d_in, const int* in_sizes, int n_in,
                              void* d_out, int out_size)
{
    (void)in_sizes; (void)n_in; (void)out_size;
    const float* x     = (const float*)d_in[0];
    const float* ln1_g = (const float*)d_in[1];
    const float* ln1_b = (const float*)d_in[2];
    const float* Wq    = (const float*)d_in[3];
    const float* bq    = (const float*)d_in[4];
    const float* Wk    = (const float*)d_in[5];
    const float* bk    = (const float*)d_in[6];
    const float* Wv    = (const float*)d_in[7];
    const float* bv    = (const float*)d_in[8];
    const float* Wo    = (const float*)d_in[9];
    const float* bo    = (const float*)d_in[10];
    const float* ln2_g = (const float*)d_in[11];
    const float* ln2_b = (const float*)d_in[12];
    const float* W1    = (const float*)d_in[13];
    const float* b1    = (const float*)d_in[14];
    const float* W2    = (const float*)d_in[15];
    const float* b2    = (const float*)d_in[16];
    const float* conv_w = (const float*)d_in[17];
    const float* conv_b = (const float*)d_in[18];
    const float* bn_g   = (const float*)d_in[19];
    const float* bn_b   = (const float*)d_in[20];
    const float* bn_mean = (const float*)d_in[21];
    const float* bn_var  = (const float*)d_in[22];
    float* out = (float*)d_out;

    static const int HEADS_H[24] = {1,2,3,4,6,9,12,18,36,
                                    1,2,3,4,6,
                                    6,9,12,18,36,
                                    3,4,6,9,12};
    static const int START[4] = {0, 9, 14, 19};
    static const int DEPTH[4] = {9, 5, 5, 5};

    const int ATTN_SMEM = (1200 * KVP + QT * 36) * 4;
    const int CONV_SMEM = (144 * 32 + 36 * 433) * 4;
    const int R2_SMEM   = R2_TOT * 4;
    const int LQ_SMEM   = LQ_TOT * 4;
    cudaFuncSetAttribute(attn_kernel, cudaFuncAttributeMaxDynamicSharedMemorySize, ATTN_SMEM);
    cudaFuncSetAttribute(conv_kernel, cudaFuncAttributeMaxDynamicSharedMemorySize, CONV_SMEM);
    cudaFuncSetAttribute(rowchain2_kernel, cudaFuncAttributeMaxDynamicSharedMemorySize, R2_SMEM);
    cudaFuncSetAttribute(lnqkv2_kernel, cudaFuncAttributeMaxDynamicSharedMemorySize, LQ_SMEM);

    embed_kernel<<<1350, 256>>>(x);

    int4 L0 = make_int4(0, 9, 14, 19);
    lnqkv2_kernel<<<dim3(75, 1, 4), 512, LQ_SMEM>>>(L0, ln1_g, ln1_b,
                                                    Wq, bq, Wk, bk, Wv, bv);

    for (int t = 0; t < 9; t++) {
        int nA = (t < 5) ? 4 : 1;
        int lc[4], nx[4], hh[4];
        for (int s = 0; s < 4; s++) {
            int L = START[s] + t;
            lc[s] = (L < 24) ? L : 0;
            hh[s] = (t < DEPTH[s]) ? HEADS_H[lc[s]] : 1;
            nx[s] = (t + 1 < DEPTH[s]) ? lc[s] + 1 : -1;
        }
        int4 Lc = make_int4(lc[0], lc[1], lc[2], lc[3]);
        int4 Nx = make_int4(nx[0], nx[1], nx[2], nx[3]);
        int4 Hh = make_int4(hh[0], hh[1], hh[2], hh[3]);

        attn_kernel<<<dim3(NTILES, 4, nA), 512, ATTN_SMEM>>>(Hh);
        rowchain2_kernel<<<dim3(38, 1, nA), 256, R2_SMEM>>>(
            Lc, Nx, Wo, bo, ln2_g, ln2_b, W1, b1, W2, b2,
            ln1_g, ln1_b, Wq, bq, Wk, bk, Wv, bv);
    }

    gate_kernel<<<16, 288>>>();
    conv_kernel<<<dim3(20, 4), 360, CONV_SMEM>>>(conv_w, conv_b, bn_g, bn_b,
                                                 bn_mean, bn_var, out);
}

// round 12
// speedup vs baseline: 1.0131x; 1.0131x over previous
#include <cuda_runtime.h>
#include <math.h>

#define NSTACK 4
#define BATCH  4
#define LSEQ   600
#define DMODEL 36
#define DFF    144
#define QT     30
#define NTILES 20
#define NI     19
#define KVP    37   // padded K/V row stride in smem (conflict-free)

// ---------------- scratch ----------------
__device__ float g_z[NSTACK*BATCH*LSEQ*DMODEL];
__device__ float g_q[NSTACK*BATCH*LSEQ*DMODEL];
__device__ float g_k[NSTACK*BATCH*LSEQ*DMODEL];
__device__ float g_v[NSTACK*BATCH*LSEQ*DMODEL];
__device__ float g_o[NSTACK*BATCH*LSEQ*DMODEL];
__device__ float g_gate[NSTACK*BATCH*DMODEL];

__device__ __forceinline__ int pick4(int4 v, int s) {
    return (s == 0) ? v.x : (s == 1) ? v.y : (s == 2) ? v.z : v.w;
}
__device__ __forceinline__ float wred(float v) {
#pragma unroll
    for (int o = 16; o > 0; o >>= 1) v += __shfl_xor_sync(0xffffffffu, v, o);
    return v;
}
__device__ __forceinline__ float ex2(float x) {
    float r;
    asm("ex2.approx.f32 %0, %1;" : "=f"(r) : "f"(x));
    return r;
}
// gelu(tanh approx) = u * sigmoid(2 * 0.79788456*(u + 0.044715 u^3))
__device__ __forceinline__ float gelu(float u) {
    float a = 1.5957691216057308f * (u + 0.044715f * u * u * u);
    return __fdividef(u, 1.f + __expf(-a));
}
__device__ __forceinline__ void cp4(float* dst, const float* __restrict__ src,
                                    int n, int tid, int nt) {
    const float4* s4 = (const float4*)src;
    float4* d4 = (float4*)dst;
    for (int i = tid; i < (n >> 2); i += nt) d4[i] = s4[i];
}

// ---------------- embedding ----------------
__global__ void embed_kernel(const float* __restrict__ x)
{
    int idx = blockIdx.x * blockDim.x + threadIdx.x;
    if (idx >= NSTACK * BATCH * LSEQ * DMODEL) return;
    int d = idx % 36;
    int l = (idx / 36) % 600;
    int b = (idx / 21600) % 4;
    int j = d >> 1;
    float freq = __expf(-logf(10000.f) * (float)(2 * j) / 36.f);
    float ang = (float)l * freq;
    float pe = (d & 1) ? cosf(ang) : sinf(ang);
    g_z[idx] = x[b * 21600 + d * 600 + l] + pe;
}

// =============================================================
// Initial LN1 + QKV: 512 threads, 16 warps, 2 rows/warp (R10)
// =============================================================
#define LQ_WQ 0
#define LQ_WK 1296
#define LQ_WV 2592
#define LQ_LG 3888
#define LQ_LB 3924
#define LQ_BQ 3960
#define LQ_BK 3996
#define LQ_BV 4032
#define LQ_YB 4068
#define LQ_TOT (4068 + 32*40)

__global__ void __launch_bounds__(512, 2) lnqkv2_kernel(
    int4 layer4,
    const float* __restrict__ ln1_g, const float* __restrict__ ln1_b,
    const float* __restrict__ Wq, const float* __restrict__ bq,
    const float* __restrict__ Wk, const float* __restrict__ bk,
    const float* __restrict__ Wv, const float* __restrict__ bv)
{
    extern __shared__ float sm[];
    int tid = threadIdx.x, lane = tid & 31, w = tid >> 5;
    int s = blockIdx.z;
    int L = pick4(layer4, s);

    cp4(sm + LQ_WQ, Wq + L * 1296, 1296, tid, 512);
    cp4(sm + LQ_WK, Wk + L * 1296, 1296, tid, 512);
    cp4(sm + LQ_WV, Wv + L * 1296, 1296, tid, 512);
    cp4(sm + LQ_LG, ln1_g + L * 36, 36, tid, 512);
    cp4(sm + LQ_LB, ln1_b + L * 36, 36, tid, 512);
    cp4(sm + LQ_BQ, bq + L * 36, 36, tid, 512);
    cp4(sm + LQ_BK, bk + L * 36, 36, tid, 512);
    cp4(sm + LQ_BV, bv + L * 36, 36, tid, 512);
    __syncthreads();

    int rA = blockIdx.x * 32 + w * 2;
    int gA = s * 2400 + rA, gB = gA + 1;
    int j = lane, j2 = lane + 32;
    bool e2 = lane < 4;
    float* bufA = sm + LQ_YB + (w * 2) * 40;
    float* bufB = bufA + 40;

    bufA[lane] = g_z[gA * 36 + lane];
    bufB[lane] = g_z[gB * 36 + lane];
    if (e2) { bufA[j2] = g_z[gA * 36 + j2]; bufB[j2] = g_z[gB * 36 + j2]; }
    __syncwarp();

    float tA0 = bufA[j], tB0 = bufB[j];
    float tA1 = e2 ? bufA[j2] : 0.f, tB1 = e2 ? bufB[j2] : 0.f;
    float sA = wred(tA0 + (e2 ? tA1 : 0.f));
    float qA = wred(tA0 * tA0 + (e2 ? tA1 * tA1 : 0.f));
    float sB = wred(tB0 + (e2 ? tB1 : 0.f));
    float qB = wred(tB0 * tB0 + (e2 ? tB1 * tB1 : 0.f));
    float mA = sA * (1.f / 36.f), mB = sB * (1.f / 36.f);
    float rsA = rsqrtf(qA * (1.f / 36.f) - mA * mA + 1e-6f);
    float rsB = rsqrtf(qB * (1.f / 36.f) - mB * mB + 1e-6f);

    bufA[j] = sm[LQ_LG + j] * (tA0 - mA) * rsA + sm[LQ_LB + j];
    bufB[j] = sm[LQ_LG + j] * (tB0 - mB) * rsB + sm[LQ_LB + j];
    if (e2) {
        bufA[j2] = sm[LQ_LG + j2] * (tA1 - mA) * rsA + sm[LQ_LB + j2];
        bufB[j2] = sm[LQ_LG + j2] * (tB1 - mB) * rsB + sm[LQ_LB + j2];
    }
    __syncwarp();

    float qA0 = sm[LQ_BQ + j], qB0 = qA0;
    float kA0 = sm[LQ_BK + j], kB0 = kA0;
    float vA0 = sm[LQ_BV + j], vB0 = vA0;
    float qA1 = 0.f, qB1 = 0.f, kA1 = 0.f, kB1 = 0.f, vA1 = 0.f, vB1 = 0.f;
    if (e2) {
        qA1 = sm[LQ_BQ + j2]; qB1 = qA1;
        kA1 = sm[LQ_BK + j2]; kB1 = kA1;
        vA1 = sm[LQ_BV + j2]; vB1 = vA1;
    }
#pragma unroll
    for (int d = 0; d < 36; d++) {
        float av = bufA[d], bvv = bufB[d];
        float wq = sm[LQ_WQ + d * 36 + j];
        float wk = sm[LQ_WK + d * 36 + j];
        float wv = sm[LQ_WV + d * 36 + j];
        qA0 = fmaf(av, wq, qA0); qB0 = fmaf(bvv, wq, qB0);
        kA0 = fmaf(av, wk, kA0); kB0 = fmaf(bvv, wk, kB0);
        vA0 = fmaf(av, wv, vA0); vB0 = fmaf(bvv, wv, vB0);
        if (e2) {
            float wq2 = sm[LQ_WQ + d * 36 + j2];
            float wk2 = sm[LQ_WK + d * 36 + j2];
            float wv2 = sm[LQ_WV + d * 36 + j2];
            qA1 = fmaf(av, wq2, qA1); qB1 = fmaf(bvv, wq2, qB1);
            kA1 = fmaf(av, wk2, kA1); kB1 = fmaf(bvv, wk2, kB1);
            vA1 = fmaf(av, wv2, vA1); vB1 = fmaf(bvv, wv2, vB1);
        }
    }
    g_q[gA * 36 + j] = qA0; g_q[gB * 36 + j] = qB0;
    g_k[gA * 36 + j] = kA0; g_k[gB * 36 + j] = kB0;
    g_v[gA * 36 + j] = vA0; g_v[gB * 36 + j] = vB0;
    if (e2) {
        g_q[gA * 36 + j2] = qA1; g_q[gB * 36 + j2] = qB1;
        g_k[gA * 36 + j2] = kA1; g_k[gB * 36 + j2] = kB1;
        g_v[gA * 36 + j2] = vA1; g_v[gB * 36 + j2] = vB1;
    }
}

// =============================================================
// rowchain v2.1: row-per-lane GEMM tiling, spill-free.
// 256 threads = 8 warps; block owns 64 rows (2 per lane).
// FFN1 chunked 2x9 cols, QKV chunked 2x7 cols (reg pressure).
// =============================================================
#define R2_WS    0
#define R2_BO    9072
#define R2_L2G   9108
#define R2_L2B   9144
#define R2_B1    9180
#define R2_B2    9324
#define R2_L1G   9360
#define R2_L1B   9396
#define R2_BQ3   9432
#define R2_BT    9540
#define R2_BY    (9540 + 64*37)
#define R2_BG    (9540 + 2*64*37)
#define R2_TOT   (9540 + 2*64*37 + 64*149)   // 23812 floats = 95.2 KB

__global__ void __launch_bounds__(256, 2) rowchain2_kernel(
    int4 layer4, int4 next4,
    const float* __restrict__ Wo, const float* __restrict__ bo,
    const float* __restrict__ ln2_g, const float* __restrict__ ln2_b,
    const float* __restrict__ W1, const float* __restrict__ b1,
    const float* __restrict__ W2, const float* __restrict__ b2,
    const float* __restrict__ ln1_g, const float* __restrict__ ln1_b,
    const float* __restrict__ Wq, const float* __restrict__ bq,
    const float* __restrict__ Wk, const float* __restrict__ bk,
    const float* __restrict__ Wv, const float* __restrict__ bv)
{
    extern __shared__ float sm[];
    int tid = threadIdx.x, lane = tid & 31, w = tid >> 5;
    int s = blockIdx.z;
    int L = pick4(layer4, s), Ln = pick4(next4, s);
    int sbase = s * 2400;
    int r0l = blockIdx.x * 64 + lane;
    int r1l = r0l + 32;
    bool v1 = (r1l < 2400);
    int g0 = sbase + r0l;
    int g1 = sbase + (v1 ? r1l : 2399);
    int lr0 = lane, lr1 = lane + 32;

    // ---- stage phase A: WO, W1, biases; o -> BUFY ----
    cp4(sm + R2_WS, Wo + L * 1296, 1296, tid, 256);
    cp4(sm + R2_WS + 1296, W1 + L * 5184, 5184, tid, 256);
    cp4(sm + R2_BO,  bo + L * 36, 36, tid, 256);
    cp4(sm + R2_L2G, ln2_g + L * 36, 36, tid, 256);
    cp4(sm + R2_L2B, ln2_b + L * 36, 36, tid, 256);
    cp4(sm + R2_B1,  b1 + L * 144, 144, tid, 256);
    cp4(sm + R2_B2,  b2 + L * 36, 36, tid, 256);
    if (Ln >= 0) {
        cp4(sm + R2_L1G, ln1_g + Ln * 36, 36, tid, 256);
        cp4(sm + R2_L1B, ln1_b + Ln * 36, 36, tid, 256);
        cp4(sm + R2_BQ3,      bq + Ln * 36, 36, tid, 256);
        cp4(sm + R2_BQ3 + 36, bk + Ln * 36, 36, tid, 256);
        cp4(sm + R2_BQ3 + 72, bv + Ln * 36, 36, tid, 256);
    }
    {
        int rowcap = 2399 - blockIdx.x * 64;
        for (int i = tid; i < 64 * 36; i += 256) {
            int lr = i / 36, c = i - lr * 36;
            int lrc = lr < rowcap ? lr : rowcap;
            sm[R2_BY + lr * 37 + c] = g_o[(sbase + blockIdx.x * 64 + lrc) * 36 + c];
        }
    }
    __syncthreads();

    int ob = (w < 6) ? 5 * w : (w == 6 ? 30 : 31);   // cols ob..ob+4, overlap benign

    // ---- o-projection + residual -> t (regs) + BUFT ----
    float t0[5], t1[5];
#pragma unroll
    for (int k = 0; k < 5; k++) { t0[k] = sm[R2_BO + ob + k]; t1[k] = t0[k]; }
#pragma unroll
    for (int d = 0; d < 36; d++) {
        float a0 = sm[R2_BY + lr0 * 37 + d];
        float a1 = sm[R2_BY + lr1 * 37 + d];
#pragma unroll
        for (int k = 0; k < 5; k++) {
            float wv = sm[R2_WS + d * 36 + ob + k];
            t0[k] = fmaf(a0, wv, t0[k]);
            t1[k] = fmaf(a1, wv, t1[k]);
        }
    }
#pragma unroll
    for (int k = 0; k < 5; k++) {
        int c = ob + k;
        t0[k] += g_z[g0 * 36 + c];
        t1[k] += g_z[g1 * 36 + c];
        sm[R2_BT + lr0 * 37 + c] = t0[k];
        sm[R2_BT + lr1 * 37 + c] = t1[k];
    }
    __syncthreads();

    // ---- LN2 (per-lane full-row stats) -> y into BUFY ----
    float m0, rs0, m1, rs1;
    {
        float s0 = 0.f, q0 = 0.f, s1 = 0.f, q1 = 0.f;
#pragma unroll
        for (int d = 0; d < 36; d++) {
            float x0 = sm[R2_BT + lr0 * 37 + d];
            float x1 = sm[R2_BT + lr1 * 37 + d];
            s0 += x0; q0 = fmaf(x0, x0, q0);
            s1 += x1; q1 = fmaf(x1, x1, q1);
        }
        m0 = s0 * (1.f / 36.f); rs0 = rsqrtf(q0 * (1.f / 36.f) - m0 * m0 + 1e-6f);
        m1 = s1 * (1.f / 36.f); rs1 = rsqrtf(q1 * (1.f / 36.f) - m1 * m1 + 1e-6f);
    }
#pragma unroll
    for (int k = 0; k < 5; k++) {
        int c = ob + k;
        sm[R2_BY + lr0 * 37 + c] = sm[R2_L2G + c] * (t0[k] - m0) * rs0 + sm[R2_L2B + c];
        sm[R2_BY + lr1 * 37 + c] = sm[R2_L2G + c] * (t1[k] - m1) * rs1 + sm[R2_L2B + c];
    }
    __syncthreads();

    // ---- FFN1 + GELU -> BUFG  (2 chunks of 9 cols: no spills) ----
#pragma unroll
    for (int half = 0; half < 2; half++) {
        int cb = w * 18 + half * 9;
        float f0[9], f1[9];
#pragma unroll
        for (int k = 0; k < 9; k++) { f0[k] = sm[R2_B1 + cb + k]; f1[k] = f0[k]; }
#pragma unroll
        for (int d = 0; d < 36; d++) {
            float a0 = sm[R2_BY + lr0 * 37 + d];
            float a1 = sm[R2_BY + lr1 * 37 + d];
#pragma unroll
            for (int k = 0; k < 9; k++) {
                float wv = sm[R2_WS + 1296 + d * 144 + cb + k];
                f0[k] = fmaf(a0, wv, f0[k]);
                f1[k] = fmaf(a1, wv, f1[k]);
            }
        }
#pragma unroll
        for (int k = 0; k < 9; k++) {
            sm[R2_BG + lr0 * 149 + cb + k] = gelu(f0[k]);
            sm[R2_BG + lr1 * 149 + cb + k] = gelu(f1[k]);
        }
    }
    __syncthreads();

    // ---- stage phase B: W2, fused WQKV (overwrite WS) ----
    cp4(sm + R2_WS, W2 + L * 5184, 5184, tid, 256);
    if (Ln >= 0) {
        const float* Wm0 = Wq + Ln * 1296;
        const float* Wm1 = Wk + Ln * 1296;
        const float* Wm2 = Wv + Ln * 1296;
        for (int i = tid; i < 1296; i += 256) {
            int d = i / 36, c = i - d * 36;
            sm[R2_WS + 5184 + d * 108 + c]      = Wm0[i];
            sm[R2_WS + 5184 + d * 108 + 36 + c] = Wm1[i];
            sm[R2_WS + 5184 + d * 108 + 72 + c] = Wm2[i];
        }
    }
    __syncthreads();

    // ---- FFN2 + residual -> z (regs) + g_z + BUFT(in place) ----
    float z0[5], z1[5];
#pragma unroll
    for (int k = 0; k < 5; k++) { z0[k] = sm[R2_B2 + ob + k]; z1[k] = z0[k]; }
#pragma unroll 8
    for (int d = 0; d < 144; d++) {
        float a0 = sm[R2_BG + lr0 * 149 + d];
        float a1 = sm[R2_BG + lr1 * 149 + d];
#pragma unroll
        for (int k = 0; k < 5; k++) {
            float wv = sm[R2_WS + d * 36 + ob + k];
            z0[k] = fmaf(a0, wv, z0[k]);
            z1[k] = fmaf(a1, wv, z1[k]);
        }
    }
#pragma unroll
    for (int k = 0; k < 5; k++) {
        int c = ob + k;
        z0[k] += t0[k]; z1[k] += t1[k];
        g_z[g0 * 36 + c] = z0[k];
        if (v1) g_z[g1 * 36 + c] = z1[k];
        sm[R2_BT + lr0 * 37 + c] = z0[k];
        sm[R2_BT + lr1 * 37 + c] = z1[k];
    }
    __syncthreads();
    if (Ln < 0) return;

    // ---- LN1 (next layer) -> y into BUFY ----
    {
        float s0 = 0.f, q0 = 0.f, s1 = 0.f, q1 = 0.f;
#pragma unroll
        for (int d = 0; d < 36; d++) {
            float x0 = sm[R2_BT + lr0 * 37 + d];
            float x1 = sm[R2_BT + lr1 * 37 + d];
            s0 += x0; q0 = fmaf(x0, x0, q0);
            s1 += x1; q1 = fmaf(x1, x1, q1);
        }
        m0 = s0 * (1.f / 36.f); rs0 = rsqrtf(q0 * (1.f / 36.f) - m0 * m0 + 1e-6f);
        m1 = s1 * (1.f / 36.f); rs1 = rsqrtf(q1 * (1.f / 36.f) - m1 * m1 + 1e-6f);
    }
#pragma unroll
    for (int k = 0; k < 5; k++) {
        int c = ob + k;
        sm[R2_BY + lr0 * 37 + c] = sm[R2_L1G + c] * (z0[k] - m0) * rs0 + sm[R2_L1B + c];
        sm[R2_BY + lr1 * 37 + c] = sm[R2_L1G + c] * (z1[k] - m1) * rs1 + sm[R2_L1B + c];
    }
    __syncthreads();

    // ---- fused QKV (next layer), 2 chunks of 7 cols ----
    {
        int qb = (w < 7) ? 14 * w : 94;
#pragma unroll
        for (int half = 0; half < 2; half++) {
            int qc = qb + half * 7;
            float acc0[7], acc1[7];
#pragma unroll
            for (int k = 0; k < 7; k++) { acc0[k] = sm[R2_BQ3 + qc + k]; acc1[k] = acc0[k]; }
#pragma unroll
            for (int d = 0; d < 36; d++) {
                float a0 = sm[R2_BY + lr0 * 37 + d];
                float a1 = sm[R2_BY + lr1 * 37 + d];
#pragma unroll
                for (int k = 0; k < 7; k++) {
                    float wv = sm[R2_WS + 5184 + d * 108 + qc + k];
                    acc0[k] = fmaf(a0, wv, acc0[k]);
                    acc1[k] = fmaf(a1, wv, acc1[k]);
                }
            }
#pragma unroll
            for (int k = 0; k < 7; k++) {
                int c = qc + k;
                float* dst = (c < 36) ? g_q : (c < 72) ? g_k : g_v;
                int col = (c < 36) ? c : (c < 72) ? c - 36 : c - 72;
                dst[g0 * 36 + col] = acc0[k];
                if (v1) dst[g1 * 36 + col] = acc1[k];
            }
        }
    }
}

// =============================================================
// attention (R10, unchanged): padded smem, online softmax, ex2
// =============================================================
template<int DK, int NQ>
__device__ __forceinline__ void attn_head_group(
    const float* __restrict__ ksh, const float* __restrict__ vsh,
    const float* __restrict__ qsh, float* __restrict__ ob,
    int q0, int g, int off, int lane)
{
    float qreg[NQ][DK];
#pragma unroll
    for (int qq = 0; qq < NQ; qq++) {
        int ql = g * NQ + qq;
#pragma unroll
        for (int d = 0; d < DK; d++)
            qreg[qq][d] = (ql < QT) ? qsh[ql * 36 + off + d] : 0.f;
    }
    float acc[NQ][DK];
    float ssum[NQ];
#pragma unroll
    for (int qq = 0; qq < NQ; qq++) {
        ssum[qq] = 0.f;
#pragma unroll
        for (int d = 0; d < DK; d++) acc[qq][d] = 0.f;
    }
    const float scale2 = rsqrtf((float)DK) * 1.44269504088896f;
    for (int i = 0; i < NI; i++) {
        int m = i * 32 + lane;
        if (m < LSEQ) {
            const float* kr = ksh + m * KVP + off;
            const float* vr = vsh + m * KVP + off;
            float p[NQ];
#pragma unroll
            for (int qq = 0; qq < NQ; qq++) p[qq] = 0.f;
#pragma unroll
            for (int d = 0; d < DK; d++) {
                float kv = kr[d];
#pragma unroll
                for (int qq = 0; qq < NQ; qq++)
                    p[qq] = fmaf(qreg[qq][d], kv, p[qq]);
            }
#pragma unroll
            for (int qq = 0; qq < NQ; qq++) {
                p[qq] = ex2(p[qq] * scale2);
                ssum[qq] += p[qq];
            }
#pragma unroll
            for (int d = 0; d < DK; d++) {
                float vv = vr[d];
#pragma unroll
                for (int qq = 0; qq < NQ; qq++)
                    acc[qq][d] = fmaf(p[qq], vv, acc[qq][d]);
            }
        }
    }
    float inv[NQ];
#pragma unroll
    for (int qq = 0; qq < NQ; qq++) {
        float sv = wred(ssum[qq]);
        inv[qq] = 1.f / sv;
    }
#pragma unroll
    for (int qq = 0; qq < NQ; qq++) {
        int ql = g * NQ + qq;
#pragma unroll
        for (int d = 0; d < DK; d++) {
            float a = wred(acc[qq][d]);
            if (ql < QT && lane == ((qq * DK + d) & 31))
                ob[(q0 + ql) * 36 + off + d] = a * inv[qq];
        }
    }
}

template<int DK, int NQ>
__device__ void attn_run(const float* ksh, const float* vsh, const float* qsh,
                         float* ob, int q0, int lane, int wid)
{
    constexpr int H  = 36 / DK;
    constexpr int NG = (QT + NQ - 1) / NQ;
    for (int u = wid; u < H * NG; u += 16) {
        int hh = u / NG, g = u % NG;
        attn_head_group<DK, NQ>(ksh, vsh, qsh, ob, q0, g, hh * DK, lane);
    }
}

__global__ void __launch_bounds__(512, 1) attn_kernel(int4 heads4)
{
    extern __shared__ float sh[];
    float* ksh = sh;
    float* vsh = sh + 600 * KVP;
    float* qsh = sh + 1200 * KVP;
    int tile = blockIdx.x, b = blockIdx.y, s = blockIdx.z;
    int h = pick4(heads4, s);
    int base = (s * 4 + b) * 21600;

    const float4* kg = (const float4*)(g_k + base);
    const float4* vg = (const float4*)(g_v + base);
    for (int i4 = threadIdx.x; i4 < 5400; i4 += 512) {
        int row = i4 / 9, c = (i4 % 9) * 4;
        float4 kv = kg[i4], vv = vg[i4];
        float* kd = ksh + row * KVP + c;
        kd[0] = kv.x; kd[1] = kv.y; kd[2] = kv.z; kd[3] = kv.w;
        float* vd = vsh + row * KVP + c;
        vd[0] = vv.x; vd[1] = vv.y; vd[2] = vv.z; vd[3] = vv.w;
    }
    int q0 = tile * QT;
    for (int i = threadIdx.x; i < QT * 36; i += 512) qsh[i] = g_q[base + q0 * 36 + i];
    __syncthreads();

    int lane = threadIdx.x & 31, wid = threadIdx.x >> 5;
    float* ob = g_o + base;
    switch (h) {
        case 1:  attn_run<36, 1>(ksh, vsh, qsh, ob, q0, lane, wid); break;
        case 2:  attn_run<18, 2>(ksh, vsh, qsh, ob, q0, lane, wid); break;
        case 3:  attn_run<12, 3>(ksh, vsh, qsh, ob, q0, lane, wid); break;
        case 4:  attn_run<9,  4>(ksh, vsh, qsh, ob, q0, lane, wid); break;
        case 6:  attn_run<6,  6>(ksh, vsh, qsh, ob, q0, lane, wid); break;
        case 9:  attn_run<4,  6>(ksh, vsh, qsh, ob, q0, lane, wid); break;
        case 12: attn_run<3,  6>(ksh, vsh, qsh, ob, q0, lane, wid); break;
        case 18: attn_run<2,  6>(ksh, vsh, qsh, ob, q0, lane, wid); break;
        case 36: attn_run<1, 10>(ksh, vsh, qsh, ob, q0, lane, wid); break;
    }
}

// ---------------- SE gate ----------------
__global__ void __launch_bounds__(288) gate_kernel()
{
    int sb = blockIdx.x;
    __shared__ float red[288];
    int t = threadIdx.x;
    int c = t / 8, k = t % 8;
    float sum = 0.f;
    const float* zz = g_z + sb * 21600;
    for (int l = k; l < 600; l += 8) sum += zz[l * 36 + c];
    red[t] = sum;
    __syncthreads();
    if (k == 0) {
        float tot = 0.f;
#pragma unroll
        for (int i = 0; i < 8; i++) tot += red[c * 8 + i];
        float mean = tot * (1.f / 600.f);
        g_gate[sb * 36 + c] = 1.f / (1.f + __expf(-mean));
    }
}

// ---------------- conv + BN + ReLU ----------------
__global__ void __launch_bounds__(360) conv_kernel(
    const float* __restrict__ conv_w, const float* __restrict__ conv_b,
    const float* __restrict__ bn_g, const float* __restrict__ bn_b,
    const float* __restrict__ bn_mean, const float* __restrict__ bn_var,
    float* __restrict__ out)
{
    extern __shared__ float esh[];
    float* xf  = esh;
    float* wsh = esh + 144 * 32;
    int b = blockIdx.y, lbase = blockIdx.x * 30;
    int t = threadIdx.x;

    for (int idx = t; idx < 144 * 32; idx += 360) {
        int i = idx >> 5, lc = idx & 31;
        int l = lbase + lc - 1;
        float val = 0.f;
        if (l >= 0 && l < 600) {
            int s = i / 36, c = i % 36;
            val = g_gate[(s * 4 + b) * 36 + c] * g_z[((s * 4 + b) * 600 + l) * 36 + c];
        }
        xf[i * 32 + lc] = val;
    }
    for (int idx = t; idx < 36 * 432; idx += 360) {
        int o = idx / 432, rest = idx % 432;
        wsh[o * 433 + rest] = conv_w[idx];
    }
    __syncthreads();

    int o = t % 36, lj = t / 36;
    float scale = bn_g[o] * rsqrtf(bn_var[o] + 1e-5f);
    float shift = bn_b[o] - scale * bn_mean[o];
    float cb = conv_b[o];
    const float* w = wsh + o * 433;
#pragma unroll
    for (int rep = 0; rep < 3; rep++) {
        int lc = lj + rep * 10;
        float acc = cb;
#pragma unroll 8
        for (int i = 0; i < 144; i++) {
            float x0 = xf[i * 32 + lc];
            float x1 = xf[i * 32 + lc + 1];
            float x2 = xf[i * 32 + lc + 2];
            acc += x0 * w[i * 3 + 0] + x1 * w[i * 3 + 1] + x2 * w[i * 3 + 2];
        }
        float y = scale * acc + shift;
        out[b * 21600 + o * 600 + lbase + lc] = fmaxf(y, 0.f);
    }
}

// ---------------- host driver ----------------
extern "C" void kernel_launch(void* const* d_in, const int* in_sizes, int n_in,
                              void* d_out, int out_size)
{
    (void)in_sizes; (void)n_in; (void)out_size;
    const float* x     = (const float*)d_in[0];
    const float* ln1_g = (const float*)d_in[1];
    const float* ln1_b = (const float*)d_in[2];
    const float* Wq    = (const float*)d_in[3];
    const float* bq    = (const float*)d_in[4];
    const float* Wk    = (const float*)d_in[5];
    const float* bk    = (const float*)d_in[6];
    const float* Wv    = (const float*)d_in[7];
    const float* bv    = (const float*)d_in[8];
    const float* Wo    = (const float*)d_in[9];
    const float* bo    = (const float*)d_in[10];
    const float* ln2_g = (const float*)d_in[11];
    const float* ln2_b = (const float*)d_in[12];
    const float* W1    = (const float*)d_in[13];
    const float* b1    = (const float*)d_in[14];
    const float* W2    = (const float*)d_in[15];
    const float* b2    = (const float*)d_in[16];
    const float* conv_w = (const float*)d_in[17];
    const float* conv_b = (const float*)d_in[18];
    const float* bn_g   = (const float*)d_in[19];
    const float* bn_b   = (const float*)d_in[20];
    const float* bn_mean = (const float*)d_in[21];
    const float* bn_var  = (const float*)d_in[22];
    float* out = (float*)d_out;

    static const int HEADS_H[24] = {1,2,3,4,6,9,12,18,36,
                                    1,2,3,4,6,
                                    6,9,12,18,36,
                                    3,4,6,9,12};
    static const int START[4] = {0, 9, 14, 19};
    static const int DEPTH[4] = {9, 5, 5, 5};

    const int ATTN_SMEM = (1200 * KVP + QT * 36) * 4;
    const int CONV_SMEM = (144 * 32 + 36 * 433) * 4;
    const int R2_SMEM   = R2_TOT * 4;
    const int LQ_SMEM   = LQ_TOT * 4;
    cudaFuncSetAttribute(attn_kernel, cudaFuncAttributeMaxDynamicSharedMemorySize, ATTN_SMEM);
    cudaFuncSetAttribute(conv_kernel, cudaFuncAttributeMaxDynamicSharedMemorySize, CONV_SMEM);
    cudaFuncSetAttribute(rowchain2_kernel, cudaFuncAttributeMaxDynamicSharedMemorySize, R2_SMEM);
    cudaFuncSetAttribute(lnqkv2_kernel, cudaFuncAttributeMaxDynamicSharedMemorySize, LQ_SMEM);

    embed_kernel<<<1350, 256>>>(x);

    int4 L0 = make_int4(0, 9, 14, 19);
    lnqkv2_kernel<<<dim3(75, 1, 4), 512, LQ_SMEM>>>(L0, ln1_g, ln1_b,
                                                    Wq, bq, Wk, bk, Wv, bv);

    for (int t = 0; t < 9; t++) {
        int nA = (t < 5) ? 4 : 1;
        int lc[4], nx[4], hh[4];
        for (int s = 0; s < 4; s++) {
            int L = START[s] + t;
            lc[s] = (L < 24) ? L : 0;
            hh[s] = (t < DEPTH[s]) ? HEADS_H[lc[s]] : 1;
            nx[s] = (t + 1 < DEPTH[s]) ? lc[s] + 1 : -1;
        }
        int4 Lc = make_int4(lc[0], lc[1], lc[2], lc[3]);
        int4 Nx = make_int4(nx[0], nx[1], nx[2], nx[3]);
        int4 Hh = make_int4(hh[0], hh[1], hh[2], hh[3]);

        attn_kernel<<<dim3(NTILES, 4, nA), 512, ATTN_SMEM>>>(Hh);
        rowchain2_kernel<<<dim3(38, 1, nA), 256, R2_SMEM>>>(
            Lc, Nx, Wo, bo, ln2_g, ln2_b, W1, b1, W2, b2,
            ln1_g, ln1_b, Wq, bq, Wk, bk, Wv, bv);
    }

    gate_kernel<<<16, 288>>>();
    conv_kernel<<<dim3(20, 4), 360, CONV_SMEM>>>(conv_w, conv_b, bn_g, bn_b,
                                                 bn_mean, bn_var, out);
}

// round 13
// speedup vs baseline: 1.0377x; 1.0242x over previous
#include <cuda_runtime.h>
#include <cuda_fp16.h>
#include <math.h>

#define NSTACK 4
#define BATCH  4
#define LSEQ   600
#define DMODEL 36
#define DFF    144
#define QT     30
#define NTILES 20
#define NI     19
#define KVPH   38   // padded K/V row stride in HALVES (19m mod 32 -> conflict-free)

// ---------------- scratch ----------------
__device__ float g_z[NSTACK*BATCH*LSEQ*DMODEL];
__device__ float g_q[NSTACK*BATCH*LSEQ*DMODEL];
__device__ float g_k[NSTACK*BATCH*LSEQ*DMODEL];
__device__ float g_v[NSTACK*BATCH*LSEQ*DMODEL];
__device__ float g_o[NSTACK*BATCH*LSEQ*DMODEL];
__device__ float g_gate[NSTACK*BATCH*DMODEL];

__device__ __forceinline__ int pick4(int4 v, int s) {
    return (s == 0) ? v.x : (s == 1) ? v.y : (s == 2) ? v.z : v.w;
}
__device__ __forceinline__ float wred(float v) {
#pragma unroll
    for (int o = 16; o > 0; o >>= 1) v += __shfl_xor_sync(0xffffffffu, v, o);
    return v;
}
__device__ __forceinline__ float ex2(float x) {
    float r;
    asm("ex2.approx.f32 %0, %1;" : "=f"(r) : "f"(x));
    return r;
}
__device__ __forceinline__ float gelu(float u) {
    float a = 1.5957691216057308f * (u + 0.044715f * u * u * u);
    return __fdividef(u, 1.f + __expf(-a));
}
__device__ __forceinline__ void cp4(float* dst, const float* __restrict__ src,
                                    int n, int tid, int nt) {
    const float4* s4 = (const float4*)src;
    float4* d4 = (float4*)dst;
    for (int i = tid; i < (n >> 2); i += nt) d4[i] = s4[i];
}
// sinusoidal PE, identical math to the reference
__device__ __forceinline__ float pe_val(int l, int d) {
    int de = d & ~1;
    float freq = __expf(-0.25584278811044947f * (float)de);  // ln(10000)/36
    float ang = (float)l * freq;
    return (d & 1) ? cosf(ang) : sinf(ang);
}

// =============================================================
// Initial LN1 + QKV with fused embedding (x^T + PE -> g_z)
// 512 threads, 16 warps, 2 rows/warp
// =============================================================
#define LQ_WQ 0
#define LQ_WK 1296
#define LQ_WV 2592
#define LQ_LG 3888
#define LQ_LB 3924
#define LQ_BQ 3960
#define LQ_BK 3996
#define LQ_BV 4032
#define LQ_YB 4068
#define LQ_TOT (4068 + 32*40)

__global__ void __launch_bounds__(512, 2) lnqkv2_kernel(
    int4 layer4, const float* __restrict__ x,
    const float* __restrict__ ln1_g, const float* __restrict__ ln1_b,
    const float* __restrict__ Wq, const float* __restrict__ bq,
    const float* __restrict__ Wk, const float* __restrict__ bk,
    const float* __restrict__ Wv, const float* __restrict__ bv)
{
    extern __shared__ float sm[];
    int tid = threadIdx.x, lane = tid & 31, w = tid >> 5;
    int s = blockIdx.z;
    int L = pick4(layer4, s);

    cp4(sm + LQ_WQ, Wq + L * 1296, 1296, tid, 512);
    cp4(sm + LQ_WK, Wk + L * 1296, 1296, tid, 512);
    cp4(sm + LQ_WV, Wv + L * 1296, 1296, tid, 512);
    cp4(sm + LQ_LG, ln1_g + L * 36, 36, tid, 512);
    cp4(sm + LQ_LB, ln1_b + L * 36, 36, tid, 512);
    cp4(sm + LQ_BQ, bq + L * 36, 36, tid, 512);
    cp4(sm + LQ_BK, bk + L * 36, 36, tid, 512);
    cp4(sm + LQ_BV, bv + L * 36, 36, tid, 512);
    __syncthreads();

    int rA = blockIdx.x * 32 + w * 2;
    int gA = s * 2400 + rA, gB = gA + 1;
    int j = lane, j2 = lane + 32;
    bool e2 = lane < 4;
    float* bufA = sm + LQ_YB + (w * 2) * 40;
    float* bufB = bufA + 40;

    // embed: z = x^T + PE (write-through to g_z for the residual stream)
    {
        int bA = rA / 600, lA = rA - bA * 600;
        int rB = rA + 1;
        int bB = rB / 600, lB = rB - bB * 600;
        float za = x[bA * 21600 + lane * 600 + lA] + pe_val(lA, lane);
        float zb = x[bB * 21600 + lane * 600 + lB] + pe_val(lB, lane);
        bufA[lane] = za; g_z[gA * 36 + lane] = za;
        bufB[lane] = zb; g_z[gB * 36 + lane] = zb;
        if (e2) {
            float za2 = x[bA * 21600 + j2 * 600 + lA] + pe_val(lA, j2);
            float zb2 = x[bB * 21600 + j2 * 600 + lB] + pe_val(lB, j2);
            bufA[j2] = za2; g_z[gA * 36 + j2] = za2;
            bufB[j2] = zb2; g_z[gB * 36 + j2] = zb2;
        }
    }
    __syncwarp();

    float tA0 = bufA[j], tB0 = bufB[j];
    float tA1 = e2 ? bufA[j2] : 0.f, tB1 = e2 ? bufB[j2] : 0.f;
    float sA = wred(tA0 + (e2 ? tA1 : 0.f));
    float qA = wred(tA0 * tA0 + (e2 ? tA1 * tA1 : 0.f));
    float sB = wred(tB0 + (e2 ? tB1 : 0.f));
    float qB = wred(tB0 * tB0 + (e2 ? tB1 * tB1 : 0.f));
    float mA = sA * (1.f / 36.f), mB = sB * (1.f / 36.f);
    float rsA = rsqrtf(qA * (1.f / 36.f) - mA * mA + 1e-6f);
    float rsB = rsqrtf(qB * (1.f / 36.f) - mB * mB + 1e-6f);

    bufA[j] = sm[LQ_LG + j] * (tA0 - mA) * rsA + sm[LQ_LB + j];
    bufB[j] = sm[LQ_LG + j] * (tB0 - mB) * rsB + sm[LQ_LB + j];
    if (e2) {
        bufA[j2] = sm[LQ_LG + j2] * (tA1 - mA) * rsA + sm[LQ_LB + j2];
        bufB[j2] = sm[LQ_LG + j2] * (tB1 - mB) * rsB + sm[LQ_LB + j2];
    }
    __syncwarp();

    float qA0 = sm[LQ_BQ + j], qB0 = qA0;
    float kA0 = sm[LQ_BK + j], kB0 = kA0;
    float vA0 = sm[LQ_BV + j], vB0 = vA0;
    float qA1 = 0.f, qB1 = 0.f, kA1 = 0.f, kB1 = 0.f, vA1 = 0.f, vB1 = 0.f;
    if (e2) {
        qA1 = sm[LQ_BQ + j2]; qB1 = qA1;
        kA1 = sm[LQ_BK + j2]; kB1 = kA1;
        vA1 = sm[LQ_BV + j2]; vB1 = vA1;
    }
#pragma unroll
    for (int d = 0; d < 36; d++) {
        float av = bufA[d], bvv = bufB[d];
        float wq = sm[LQ_WQ + d * 36 + j];
        float wk = sm[LQ_WK + d * 36 + j];
        float wv = sm[LQ_WV + d * 36 + j];
        qA0 = fmaf(av, wq, qA0); qB0 = fmaf(bvv, wq, qB0);
        kA0 = fmaf(av, wk, kA0); kB0 = fmaf(bvv, wk, kB0);
        vA0 = fmaf(av, wv, vA0); vB0 = fmaf(bvv, wv, vB0);
        if (e2) {
            float wq2 = sm[LQ_WQ + d * 36 + j2];
            float wk2 = sm[LQ_WK + d * 36 + j2];
            float wv2 = sm[LQ_WV + d * 36 + j2];
            qA1 = fmaf(av, wq2, qA1); qB1 = fmaf(bvv, wq2, qB1);
            kA1 = fmaf(av, wk2, kA1); kB1 = fmaf(bvv, wk2, kB1);
            vA1 = fmaf(av, wv2, vA1); vB1 = fmaf(bvv, wv2, vB1);
        }
    }
    g_q[gA * 36 + j] = qA0; g_q[gB * 36 + j] = qB0;
    g_k[gA * 36 + j] = kA0; g_k[gB * 36 + j] = kB0;
    g_v[gA * 36 + j] = vA0; g_v[gB * 36 + j] = vB0;
    if (e2) {
        g_q[gA * 36 + j2] = qA1; g_q[gB * 36 + j2] = qB1;
        g_k[gA * 36 + j2] = kA1; g_k[gB * 36 + j2] = kB1;
        g_v[gA * 36 + j2] = vA1; g_v[gB * 36 + j2] = vB1;
    }
}

// =============================================================
// Fused row chain (R10 v1, proven 45.3us / 64 regs):
// 512 threads = 16 warps = 32 rows
// =============================================================
#define RC_WO   0
#define RC_W1   1296
#define RC_W2   6480
#define RC_WQ   11664
#define RC_WK   12960
#define RC_WV   14256
#define RC_BO   15552
#define RC_L2G  15588
#define RC_L2B  15624
#define RC_B2   15660
#define RC_B1   15696
#define RC_L1G  15840
#define RC_L1B  15876
#define RC_BQ   15912
#define RC_BK   15948
#define RC_BV   15984
#define RC_YB   16020
#define RC_GB   (16020 + 32*40)
#define RC_TOT  (RC_GB + 32*144)

__global__ void __launch_bounds__(512, 2) rowchain_kernel(
    int4 layer4, int4 next4,
    const float* __restrict__ Wo, const float* __restrict__ bo,
    const float* __restrict__ ln2_g, const float* __restrict__ ln2_b,
    const float* __restrict__ W1, const float* __restrict__ b1,
    const float* __restrict__ W2, const float* __restrict__ b2,
    const float* __restrict__ ln1_g, const float* __restrict__ ln1_b,
    const float* __restrict__ Wq, const float* __restrict__ bq,
    const float* __restrict__ Wk, const float* __restrict__ bk,
    const float* __restrict__ Wv, const float* __restrict__ bv)
{
    extern __shared__ float sm[];
    int tid = threadIdx.x, lane = tid & 31, w = tid >> 5;
    int s = blockIdx.z;
    int L = pick4(layer4, s);
    int Ln = pick4(next4, s);

    cp4(sm + RC_WO, Wo + L * 1296, 1296, tid, 512);
    cp4(sm + RC_W1, W1 + L * 5184, 5184, tid, 512);
    cp4(sm + RC_W2, W2 + L * 5184, 5184, tid, 512);
    cp4(sm + RC_BO, bo + L * 36, 36, tid, 512);
    cp4(sm + RC_L2G, ln2_g + L * 36, 36, tid, 512);
    cp4(sm + RC_L2B, ln2_b + L * 36, 36, tid, 512);
    cp4(sm + RC_B2, b2 + L * 36, 36, tid, 512);
    cp4(sm + RC_B1, b1 + L * 144, 144, tid, 512);
    if (Ln >= 0) {
        cp4(sm + RC_WQ, Wq + Ln * 1296, 1296, tid, 512);
        cp4(sm + RC_WK, Wk + Ln * 1296, 1296, tid, 512);
        cp4(sm + RC_WV, Wv + Ln * 1296, 1296, tid, 512);
        cp4(sm + RC_L1G, ln1_g + Ln * 36, 36, tid, 512);
        cp4(sm + RC_L1B, ln1_b + Ln * 36, 36, tid, 512);
        cp4(sm + RC_BQ, bq + Ln * 36, 36, tid, 512);
        cp4(sm + RC_BK, bk + Ln * 36, 36, tid, 512);
        cp4(sm + RC_BV, bv + Ln * 36, 36, tid, 512);
    }
    __syncthreads();

    int rA = blockIdx.x * 32 + w * 2;
    int gA = s * 2400 + rA, gB = gA + 1;
    int j = lane, j2 = lane + 32;
    bool e2 = lane < 4;
    bool e16 = lane < 16;
    float* bufA = sm + RC_YB + (w * 2) * 40;
    float* bufB = bufA + 40;
    float* gbA  = sm + RC_GB + (w * 2) * 144;
    float* gbB  = gbA + 144;

    bufA[lane] = g_o[gA * 36 + lane];
    bufB[lane] = g_o[gB * 36 + lane];
    if (e2) { bufA[j2] = g_o[gA * 36 + j2]; bufB[j2] = g_o[gB * 36 + j2]; }
    __syncwarp();

    float zA0 = g_z[gA * 36 + j], zB0 = g_z[gB * 36 + j];
    float zA1 = e2 ? g_z[gA * 36 + j2] : 0.f;
    float zB1 = e2 ? g_z[gB * 36 + j2] : 0.f;

    float tA0 = sm[RC_BO + j], tB0 = tA0;
    float tA1 = 0.f, tB1 = 0.f;
    if (e2) { tA1 = sm[RC_BO + j2]; tB1 = tA1; }
#pragma unroll
    for (int d = 0; d < 36; d++) {
        float av = bufA[d], bvv = bufB[d];
        float wv = sm[RC_WO + d * 36 + j];
        tA0 = fmaf(av, wv, tA0);
        tB0 = fmaf(bvv, wv, tB0);
        if (e2) {
            float wv2 = sm[RC_WO + d * 36 + j2];
            tA1 = fmaf(av, wv2, tA1);
            tB1 = fmaf(bvv, wv2, tB1);
        }
    }
    tA0 += zA0; tB0 += zB0; tA1 += zA1; tB1 += zB1;

    {
        float sA = wred(tA0 + (e2 ? tA1 : 0.f));
        float qA = wred(tA0 * tA0 + (e2 ? tA1 * tA1 : 0.f));
        float sB = wred(tB0 + (e2 ? tB1 : 0.f));
        float qB = wred(tB0 * tB0 + (e2 ? tB1 * tB1 : 0.f));
        float mA = sA * (1.f / 36.f), mB = sB * (1.f / 36.f);
        float rsA = rsqrtf(qA * (1.f / 36.f) - mA * mA + 1e-6f);
        float rsB = rsqrtf(qB * (1.f / 36.f) - mB * mB + 1e-6f);
        bufA[j] = sm[RC_L2G + j] * (tA0 - mA) * rsA + sm[RC_L2B + j];
        bufB[j] = sm[RC_L2G + j] * (tB0 - mB) * rsB + sm[RC_L2B + j];
        if (e2) {
            bufA[j2] = sm[RC_L2G + j2] * (tA1 - mA) * rsA + sm[RC_L2B + j2];
            bufB[j2] = sm[RC_L2G + j2] * (tB1 - mB) * rsB + sm[RC_L2B + j2];
        }
    }
    __syncwarp();

    {
        float fA[5], fB[5];
#pragma unroll
        for (int k = 0; k < 4; k++) {
            fA[k] = sm[RC_B1 + lane + 32 * k];
            fB[k] = fA[k];
        }
        fA[4] = e16 ? sm[RC_B1 + 128 + lane] : 0.f;
        fB[4] = fA[4];
#pragma unroll
        for (int d = 0; d < 36; d++) {
            float va = bufA[d], vb = bufB[d];
#pragma unroll
            for (int k = 0; k < 4; k++) {
                float wv = sm[RC_W1 + d * 144 + lane + 32 * k];
                fA[k] = fmaf(va, wv, fA[k]);
                fB[k] = fmaf(vb, wv, fB[k]);
            }
            if (e16) {
                float wv = sm[RC_W1 + d * 144 + 128 + lane];
                fA[4] = fmaf(va, wv, fA[4]);
                fB[4] = fmaf(vb, wv, fB[4]);
            }
        }
#pragma unroll
        for (int k = 0; k < 4; k++) {
            gbA[lane + 32 * k] = gelu(fA[k]);
            gbB[lane + 32 * k] = gelu(fB[k]);
        }
        if (e16) {
            gbA[128 + lane] = gelu(fA[4]);
            gbB[128 + lane] = gelu(fB[4]);
        }
    }
    __syncwarp();

    float znA0, znB0, znA1 = 0.f, znB1 = 0.f;
    {
        float oA0 = sm[RC_B2 + j], oB0 = oA0;
        float oA1 = 0.f, oB1 = 0.f;
        if (e2) { oA1 = sm[RC_B2 + j2]; oB1 = oA1; }
#pragma unroll 6
        for (int d = 0; d < 144; d++) {
            float ga = gbA[d], gb = gbB[d];
            float wv = sm[RC_W2 + d * 36 + j];
            oA0 = fmaf(ga, wv, oA0);
            oB0 = fmaf(gb, wv, oB0);
            if (e2) {
                float wv2 = sm[RC_W2 + d * 36 + j2];
                oA1 = fmaf(ga, wv2, oA1);
                oB1 = fmaf(gb, wv2, oB1);
            }
        }
        znA0 = oA0 + tA0; znB0 = oB0 + tB0;
        znA1 = oA1 + tA1; znB1 = oB1 + tB1;
    }
    g_z[gA * 36 + j] = znA0;
    g_z[gB * 36 + j] = znB0;
    if (e2) { g_z[gA * 36 + j2] = znA1; g_z[gB * 36 + j2] = znB1; }

    if (Ln < 0) return;

    {
        float sA = wred(znA0 + (e2 ? znA1 : 0.f));
        float qA = wred(znA0 * znA0 + (e2 ? znA1 * znA1 : 0.f));
        float sB = wred(znB0 + (e2 ? znB1 : 0.f));
        float qB = wred(znB0 * znB0 + (e2 ? znB1 * znB1 : 0.f));
        float mA = sA * (1.f / 36.f), mB = sB * (1.f / 36.f);
        float rsA = rsqrtf(qA * (1.f / 36.f) - mA * mA + 1e-6f);
        float rsB = rsqrtf(qB * (1.f / 36.f) - mB * mB + 1e-6f);
        bufA[j] = sm[RC_L1G + j] * (znA0 - mA) * rsA + sm[RC_L1B + j];
        bufB[j] = sm[RC_L1G + j] * (znB0 - mB) * rsB + sm[RC_L1B + j];
        if (e2) {
            bufA[j2] = sm[RC_L1G + j2] * (znA1 - mA) * rsA + sm[RC_L1B + j2];
            bufB[j2] = sm[RC_L1G + j2] * (znB1 - mB) * rsB + sm[RC_L1B + j2];
        }
    }
    __syncwarp();

    {
        float qA0 = sm[RC_BQ + j], qB0 = qA0;
        float kA0 = sm[RC_BK + j], kB0 = kA0;
        float vA0 = sm[RC_BV + j], vB0 = vA0;
        float qA1 = 0.f, qB1 = 0.f, kA1 = 0.f, kB1 = 0.f, vA1 = 0.f, vB1 = 0.f;
        if (e2) {
            qA1 = sm[RC_BQ + j2]; qB1 = qA1;
            kA1 = sm[RC_BK + j2]; kB1 = kA1;
            vA1 = sm[RC_BV + j2]; vB1 = vA1;
        }
#pragma unroll
        for (int d = 0; d < 36; d++) {
            float av = bufA[d], bvv = bufB[d];
            float wq = sm[RC_WQ + d * 36 + j];
            float wk = sm[RC_WK + d * 36 + j];
            float wv = sm[RC_WV + d * 36 + j];
            qA0 = fmaf(av, wq, qA0); qB0 = fmaf(bvv, wq, qB0);
            kA0 = fmaf(av, wk, kA0); kB0 = fmaf(bvv, wk, kB0);
            vA0 = fmaf(av, wv, vA0); vB0 = fmaf(bvv, wv, vB0);
            if (e2) {
                float wq2 = sm[RC_WQ + d * 36 + j2];
                float wk2 = sm[RC_WK + d * 36 + j2];
                float wv2 = sm[RC_WV + d * 36 + j2];
                qA1 = fmaf(av, wq2, qA1); qB1 = fmaf(bvv, wq2, qB1);
                kA1 = fmaf(av, wk2, kA1); kB1 = fmaf(bvv, wk2, kB1);
                vA1 = fmaf(av, wv2, vA1); vB1 = fmaf(bvv, wv2, vB1);
            }
        }
        g_q[gA * 36 + j] = qA0; g_q[gB * 36 + j] = qB0;
        g_k[gA * 36 + j] = kA0; g_k[gB * 36 + j] = kB0;
        g_v[gA * 36 + j] = vA0; g_v[gB * 36 + j] = vB0;
        if (e2) {
            g_q[gA * 36 + j2] = qA1; g_q[gB * 36 + j2] = qB1;
            g_k[gA * 36 + j2] = kA1; g_k[gB * 36 + j2] = kB1;
            g_v[gA * 36 + j2] = vA1; g_v[gB * 36 + j2] = vB1;
        }
    }
}

// =============================================================
// attention: fp16 K/V in smem (95.5KB -> 2 blocks/SM),
// 384 threads, online softmax, ex2
// =============================================================
#define NWARP 12

template<int DK, int NQ>
__device__ __forceinline__ void attn_head_group(
    const __half* __restrict__ ksh, const __half* __restrict__ vsh,
    const float* __restrict__ qsh, float* __restrict__ ob,
    int q0, int g, int off, int lane)
{
    float qreg[NQ][DK];
#pragma unroll
    for (int qq = 0; qq < NQ; qq++) {
        int ql = g * NQ + qq;
#pragma unroll
        for (int d = 0; d < DK; d++)
            qreg[qq][d] = (ql < QT) ? qsh[ql * 36 + off + d] : 0.f;
    }
    float acc[NQ][DK];
    float ssum[NQ];
#pragma unroll
    for (int qq = 0; qq < NQ; qq++) {
        ssum[qq] = 0.f;
#pragma unroll
        for (int d = 0; d < DK; d++) acc[qq][d] = 0.f;
    }
    const float scale2 = rsqrtf((float)DK) * 1.44269504088896f;
    for (int i = 0; i < NI; i++) {
        int m = i * 32 + lane;
        if (m < LSEQ) {
            const __half* kr = ksh + m * KVPH + off;
            const __half* vr = vsh + m * KVPH + off;
            float p[NQ];
#pragma unroll
            for (int qq = 0; qq < NQ; qq++) p[qq] = 0.f;
#pragma unroll
            for (int d = 0; d < DK; d++) {
                float kv = __half2float(kr[d]);
#pragma unroll
                for (int qq = 0; qq < NQ; qq++)
                    p[qq] = fmaf(qreg[qq][d], kv, p[qq]);
            }
#pragma unroll
            for (int qq = 0; qq < NQ; qq++) {
                p[qq] = ex2(p[qq] * scale2);
                ssum[qq] += p[qq];
            }
#pragma unroll
            for (int d = 0; d < DK; d++) {
                float vv = __half2float(vr[d]);
#pragma unroll
                for (int qq = 0; qq < NQ; qq++)
                    acc[qq][d] = fmaf(p[qq], vv, acc[qq][d]);
            }
        }
    }
    float inv[NQ];
#pragma unroll
    for (int qq = 0; qq < NQ; qq++) {
        float sv = wred(ssum[qq]);
        inv[qq] = 1.f / sv;
    }
#pragma unroll
    for (int qq = 0; qq < NQ; qq++) {
        int ql = g * NQ + qq;
#pragma unroll
        for (int d = 0; d < DK; d++) {
            float a = wred(acc[qq][d]);
            if (ql < QT && lane == ((qq * DK + d) & 31))
                ob[(q0 + ql) * 36 + off + d] = a * inv[qq];
        }
    }
}

template<int DK, int NQ>
__device__ void attn_run(const __half* ksh, const __half* vsh, const float* qsh,
                         float* ob, int q0, int lane, int wid)
{
    constexpr int H  = 36 / DK;
    constexpr int NG = (QT + NQ - 1) / NQ;
    for (int u = wid; u < H * NG; u += NWARP) {
        int hh = u / NG, g = u % NG;
        attn_head_group<DK, NQ>(ksh, vsh, qsh, ob, q0, g, hh * DK, lane);
    }
}

__global__ void __launch_bounds__(384, 2) attn_kernel(int4 heads4)
{
    extern __shared__ char shraw[];
    __half* ksh = (__half*)shraw;
    __half* vsh = ksh + 600 * KVPH;
    float* qsh = (float*)(shraw + 1200 * KVPH * 2);
    int tile = blockIdx.x, b = blockIdx.y, s = blockIdx.z;
    int h = pick4(heads4, s);
    int base = (s * 4 + b) * 21600;

    const float4* kg = (const float4*)(g_k + base);
    const float4* vg = (const float4*)(g_v + base);
    for (int i4 = threadIdx.x; i4 < 5400; i4 += 384) {
        int row = i4 / 9, c = (i4 % 9) * 4;
        float4 kv = kg[i4], vv = vg[i4];
        __half2* kd = (__half2*)(ksh + row * KVPH + c);
        kd[0] = __floats2half2_rn(kv.x, kv.y);
        kd[1] = __floats2half2_rn(kv.z, kv.w);
        __half2* vd = (__half2*)(vsh + row * KVPH + c);
        vd[0] = __floats2half2_rn(vv.x, vv.y);
        vd[1] = __floats2half2_rn(vv.z, vv.w);
    }
    int q0 = tile * QT;
    for (int i = threadIdx.x; i < QT * 36; i += 384) qsh[i] = g_q[base + q0 * 36 + i];
    __syncthreads();

    int lane = threadIdx.x & 31, wid = threadIdx.x >> 5;
    float* ob = g_o + base;
    switch (h) {
        case 1:  attn_run<36, 1>(ksh, vsh, qsh, ob, q0, lane, wid); break;
        case 2:  attn_run<18, 2>(ksh, vsh, qsh, ob, q0, lane, wid); break;
        case 3:  attn_run<12, 2>(ksh, vsh, qsh, ob, q0, lane, wid); break;
        case 4:  attn_run<9,  3>(ksh, vsh, qsh, ob, q0, lane, wid); break;
        case 6:  attn_run<6,  4>(ksh, vsh, qsh, ob, q0, lane, wid); break;
        case 9:  attn_run<4,  6>(ksh, vsh, qsh, ob, q0, lane, wid); break;
        case 12: attn_run<3,  6>(ksh, vsh, qsh, ob, q0, lane, wid); break;
        case 18: attn_run<2,  8>(ksh, vsh, qsh, ob, q0, lane, wid); break;
        case 36: attn_run<1, 10>(ksh, vsh, qsh, ob, q0, lane, wid); break;
    }
}

// ---------------- SE gate ----------------
__global__ void __launch_bounds__(288) gate_kernel()
{
    int sb = blockIdx.x;
    __shared__ float red[288];
    int t = threadIdx.x;
    int c = t / 8, k = t % 8;
    float sum = 0.f;
    const float* zz = g_z + sb * 21600;
    for (int l = k; l < 600; l += 8) sum += zz[l * 36 + c];
    red[t] = sum;
    __syncthreads();
    if (k == 0) {
        float tot = 0.f;
#pragma unroll
        for (int i = 0; i < 8; i++) tot += red[c * 8 + i];
        float mean = tot * (1.f / 600.f);
        g_gate[sb * 36 + c] = 1.f / (1.f + __expf(-mean));
    }
}

// ---------------- conv + BN + ReLU ----------------
__global__ void __launch_bounds__(360) conv_kernel(
    const float* __restrict__ conv_w, const float* __restrict__ conv_b,
    const float* __restrict__ bn_g, const float* __restrict__ bn_b,
    const float* __restrict__ bn_mean, const float* __restrict__ bn_var,
    float* __restrict__ out)
{
    extern __shared__ float esh[];
    float* xf  = esh;
    float* wsh = esh + 144 * 32;
    int b = blockIdx.y, lbase = blockIdx.x * 30;
    int t = threadIdx.x;

    for (int idx = t; idx < 144 * 32; idx += 360) {
        int i = idx >> 5, lc = idx & 31;
        int l = lbase + lc - 1;
        float val = 0.f;
        if (l >= 0 && l < 600) {
            int s = i / 36, c = i % 36;
            val = g_gate[(s * 4 + b) * 36 + c] * g_z[((s * 4 + b) * 600 + l) * 36 + c];
        }
        xf[i * 32 + lc] = val;
    }
    for (int idx = t; idx < 36 * 432; idx += 360) {
        int o = idx / 432, rest = idx % 432;
        wsh[o * 433 + rest] = conv_w[idx];
    }
    __syncthreads();

    int o = t % 36, lj = t / 36;
    float scale = bn_g[o] * rsqrtf(bn_var[o] + 1e-5f);
    float shift = bn_b[o] - scale * bn_mean[o];
    float cb = conv_b[o];
    const float* w = wsh + o * 433;
#pragma unroll
    for (int rep = 0; rep < 3; rep++) {
        int lc = lj + rep * 10;
        float acc = cb;
#pragma unroll 8
        for (int i = 0; i < 144; i++) {
            float x0 = xf[i * 32 + lc];
            float x1 = xf[i * 32 + lc + 1];
            float x2 = xf[i * 32 + lc + 2];
            acc += x0 * w[i * 3 + 0] + x1 * w[i * 3 + 1] + x2 * w[i * 3 + 2];
        }
        float y = scale * acc + shift;
        out[b * 21600 + o * 600 + lbase + lc] = fmaxf(y, 0.f);
    }
}

// ---------------- host driver ----------------
extern "C" void kernel_launch(void* const* d_in, const int* in_sizes, int n_in,
                              void* d_out, int out_size)
{
    (void)in_sizes; (void)n_in; (void)out_size;
    const float* x     = (const float*)d_in[0];
    const float* ln1_g = (const float*)d_in[1];
    const float* ln1_b = (const float*)d_in[2];
    const float* Wq    = (const float*)d_in[3];
    const float* bq    = (const float*)d_in[4];
    const float* Wk    = (const float*)d_in[5];
    const float* bk    = (const float*)d_in[6];
    const float* Wv    = (const float*)d_in[7];
    const float* bv    = (const float*)d_in[8];
    const float* Wo    = (const float*)d_in[9];
    const float* bo    = (const float*)d_in[10];
    const float* ln2_g = (const float*)d_in[11];
    const float* ln2_b = (const float*)d_in[12];
    const float* W1    = (const float*)d_in[13];
    const float* b1    = (const float*)d_in[14];
    const float* W2    = (const float*)d_in[15];
    const float* b2    = (const float*)d_in[16];
    const float* conv_w = (const float*)d_in[17];
    const float* conv_b = (const float*)d_in[18];
    const float* bn_g   = (const float*)d_in[19];
    const float* bn_b   = (const float*)d_in[20];
    const float* bn_mean = (const float*)d_in[21];
    const float* bn_var  = (const float*)d_in[22];
    float* out = (float*)d_out;

    static const int HEADS_H[24] = {1,2,3,4,6,9,12,18,36,
                                    1,2,3,4,6,
                                    6,9,12,18,36,
                                    3,4,6,9,12};
    static const int START[4] = {0, 9, 14, 19};
    static const int DEPTH[4] = {9, 5, 5, 5};

    const int ATTN_SMEM = 1200 * KVPH * 2 + QT * 36 * 4;   // 95,520 B
    const int CONV_SMEM = (144 * 32 + 36 * 433) * 4;
    const int RC_SMEM   = RC_TOT * 4;
    const int LQ_SMEM   = LQ_TOT * 4;
    cudaFuncSetAttribute(attn_kernel, cudaFuncAttributeMaxDynamicSharedMemorySize, ATTN_SMEM);
    cudaFuncSetAttribute(conv_kernel, cudaFuncAttributeMaxDynamicSharedMemorySize, CONV_SMEM);
    cudaFuncSetAttribute(rowchain_kernel, cudaFuncAttributeMaxDynamicSharedMemorySize, RC_SMEM);
    cudaFuncSetAttribute(lnqkv2_kernel, cudaFuncAttributeMaxDynamicSharedMemorySize, LQ_SMEM);

    int4 L0 = make_int4(0, 9, 14, 19);
    lnqkv2_kernel<<<dim3(75, 1, 4), 512, LQ_SMEM>>>(L0, x, ln1_g, ln1_b,
                                                    Wq, bq, Wk, bk, Wv, bv);

    for (int t = 0; t < 9; t++) {
        int nA = (t < 5) ? 4 : 1;
        int lc[4], nx[4], hh[4];
        for (int s = 0; s < 4; s++) {
            int L = START[s] + t;
            lc[s] = (L < 24) ? L : 0;
            hh[s] = (t < DEPTH[s]) ? HEADS_H[lc[s]] : 1;
            nx[s] = (t + 1 < DEPTH[s]) ? lc[s] + 1 : -1;
        }
        int4 Lc = make_int4(lc[0], lc[1], lc[2], lc[3]);
        int4 Nx = make_int4(nx[0], nx[1], nx[2], nx[3]);
        int4 Hh = make_int4(hh[0], hh[1], hh[2], hh[3]);

        attn_kernel<<<dim3(NTILES, 4, nA), 384, ATTN_SMEM>>>(Hh);
        rowchain_kernel<<<dim3(75, 1, nA), 512, RC_SMEM>>>(
            Lc, Nx, Wo, bo, ln2_g, ln2_b, W1, b1, W2, b2,
            ln1_g, ln1_b, Wq, bq, Wk, bk, Wv, bv);
    }

    gate_kernel<<<16, 288>>>();
    conv_kernel<<<dim3(20, 4), 360, CONV_SMEM>>>(conv_w, conv_b, bn_g, bn_b,
                                                 bn_mean, bn_var, out);
}

// round 14
// speedup vs baseline: 1.0564x; 1.0180x over previous
#include <cuda_runtime.h>
#include <math.h>

#define NSTACK 4
#define BATCH  4
#define LSEQ   600
#define DMODEL 36
#define DFF    144
#define QT     30
#define NTILES 20
#define NI     19
#define KVP    37
#define NWARP  16

// ---------------- scratch ----------------
__device__ float g_z[NSTACK*BATCH*LSEQ*DMODEL];
__device__ float g_q[NSTACK*BATCH*LSEQ*DMODEL];
__device__ float g_k[NSTACK*BATCH*LSEQ*DMODEL];
__device__ float g_v[NSTACK*BATCH*LSEQ*DMODEL];
__device__ float g_o[NSTACK*BATCH*LSEQ*DMODEL];
__device__ float g_gate[NSTACK*BATCH*DMODEL];

__device__ __forceinline__ int pick4(int4 v, int s) {
    return (s == 0) ? v.x : (s == 1) ? v.y : (s == 2) ? v.z : v.w;
}
__device__ __forceinline__ float wred(float v) {
#pragma unroll
    for (int o = 16; o > 0; o >>= 1) v += __shfl_xor_sync(0xffffffffu, v, o);
    return v;
}
__device__ __forceinline__ float ex2(float x) {
    float r;
    asm("ex2.approx.f32 %0, %1;" : "=f"(r) : "f"(x));
    return r;
}
__device__ __forceinline__ float gelu(float u) {
    float a = 1.5957691216057308f * (u + 0.044715f * u * u * u);
    return __fdividef(u, 1.f + __expf(-a));
}
__device__ __forceinline__ void cp4(float* dst, const float* __restrict__ src,
                                    int n, int tid, int nt) {
    const float4* s4 = (const float4*)src;
    float4* d4 = (float4*)dst;
    for (int i = tid; i < (n >> 2); i += nt) d4[i] = s4[i];
}
__device__ __forceinline__ float pe_val(int l, int d) {
    int de = d & ~1;
    float freq = __expf(-0.25584278811044947f * (float)de);
    float ang = (float)l * freq;
    return (d & 1) ? cosf(ang) : sinf(ang);
}

// =============================================================
// Initial LN1 + QKV with fused embedding (x^T + PE -> g_z)
// =============================================================
#define LQ_WQ 0
#define LQ_WK 1296
#define LQ_WV 2592
#define LQ_LG 3888
#define LQ_LB 3924
#define LQ_BQ 3960
#define LQ_BK 3996
#define LQ_BV 4032
#define LQ_YB 4068
#define LQ_TOT (4068 + 32*40)

__global__ void __launch_bounds__(512, 2) lnqkv2_kernel(
    int4 layer4, const float* __restrict__ x,
    const float* __restrict__ ln1_g, const float* __restrict__ ln1_b,
    const float* __restrict__ Wq, const float* __restrict__ bq,
    const float* __restrict__ Wk, const float* __restrict__ bk,
    const float* __restrict__ Wv, const float* __restrict__ bv)
{
    extern __shared__ float sm[];
    int tid = threadIdx.x, lane = tid & 31, w = tid >> 5;
    int s = blockIdx.z;
    int L = pick4(layer4, s);

    cp4(sm + LQ_WQ, Wq + L * 1296, 1296, tid, 512);
    cp4(sm + LQ_WK, Wk + L * 1296, 1296, tid, 512);
    cp4(sm + LQ_WV, Wv + L * 1296, 1296, tid, 512);
    cp4(sm + LQ_LG, ln1_g + L * 36, 36, tid, 512);
    cp4(sm + LQ_LB, ln1_b + L * 36, 36, tid, 512);
    cp4(sm + LQ_BQ, bq + L * 36, 36, tid, 512);
    cp4(sm + LQ_BK, bk + L * 36, 36, tid, 512);
    cp4(sm + LQ_BV, bv + L * 36, 36, tid, 512);
    __syncthreads();

    int rA = blockIdx.x * 32 + w * 2;
    int gA = s * 2400 + rA, gB = gA + 1;
    int j = lane, j2 = lane + 32;
    bool e2 = lane < 4;
    float* bufA = sm + LQ_YB + (w * 2) * 40;
    float* bufB = bufA + 40;

    {
        int bA = rA / 600, lA = rA - bA * 600;
        int rB = rA + 1;
        int bB = rB / 600, lB = rB - bB * 600;
        float za = x[bA * 21600 + lane * 600 + lA] + pe_val(lA, lane);
        float zb = x[bB * 21600 + lane * 600 + lB] + pe_val(lB, lane);
        bufA[lane] = za; g_z[gA * 36 + lane] = za;
        bufB[lane] = zb; g_z[gB * 36 + lane] = zb;
        if (e2) {
            float za2 = x[bA * 21600 + j2 * 600 + lA] + pe_val(lA, j2);
            float zb2 = x[bB * 21600 + j2 * 600 + lB] + pe_val(lB, j2);
            bufA[j2] = za2; g_z[gA * 36 + j2] = za2;
            bufB[j2] = zb2; g_z[gB * 36 + j2] = zb2;
        }
    }
    __syncwarp();

    float tA0 = bufA[j], tB0 = bufB[j];
    float tA1 = e2 ? bufA[j2] : 0.f, tB1 = e2 ? bufB[j2] : 0.f;
    float sA = wred(tA0 + (e2 ? tA1 : 0.f));
    float qA = wred(tA0 * tA0 + (e2 ? tA1 * tA1 : 0.f));
    float sB = wred(tB0 + (e2 ? tB1 : 0.f));
    float qB = wred(tB0 * tB0 + (e2 ? tB1 * tB1 : 0.f));
    float mA = sA * (1.f / 36.f), mB = sB * (1.f / 36.f);
    float rsA = rsqrtf(qA * (1.f / 36.f) - mA * mA + 1e-6f);
    float rsB = rsqrtf(qB * (1.f / 36.f) - mB * mB + 1e-6f);

    bufA[j] = sm[LQ_LG + j] * (tA0 - mA) * rsA + sm[LQ_LB + j];
    bufB[j] = sm[LQ_LG + j] * (tB0 - mB) * rsB + sm[LQ_LB + j];
    if (e2) {
        bufA[j2] = sm[LQ_LG + j2] * (tA1 - mA) * rsA + sm[LQ_LB + j2];
        bufB[j2] = sm[LQ_LG + j2] * (tB1 - mB) * rsB + sm[LQ_LB + j2];
    }
    __syncwarp();

    float qA0 = sm[LQ_BQ + j], qB0 = qA0;
    float kA0 = sm[LQ_BK + j], kB0 = kA0;
    float vA0 = sm[LQ_BV + j], vB0 = vA0;
    float qA1 = 0.f, qB1 = 0.f, kA1 = 0.f, kB1 = 0.f, vA1 = 0.f, vB1 = 0.f;
    if (e2) {
        qA1 = sm[LQ_BQ + j2]; qB1 = qA1;
        kA1 = sm[LQ_BK + j2]; kB1 = kA1;
        vA1 = sm[LQ_BV + j2]; vB1 = vA1;
    }
#pragma unroll
    for (int d = 0; d < 36; d++) {
        float av = bufA[d], bvv = bufB[d];
        float wq = sm[LQ_WQ + d * 36 + j];
        float wk = sm[LQ_WK + d * 36 + j];
        float wv = sm[LQ_WV + d * 36 + j];
        qA0 = fmaf(av, wq, qA0); qB0 = fmaf(bvv, wq, qB0);
        kA0 = fmaf(av, wk, kA0); kB0 = fmaf(bvv, wk, kB0);
        vA0 = fmaf(av, wv, vA0); vB0 = fmaf(bvv, wv, vB0);
        if (e2) {
            float wq2 = sm[LQ_WQ + d * 36 + j2];
            float wk2 = sm[LQ_WK + d * 36 + j2];
            float wv2 = sm[LQ_WV + d * 36 + j2];
            qA1 = fmaf(av, wq2, qA1); qB1 = fmaf(bvv, wq2, qB1);
            kA1 = fmaf(av, wk2, kA1); kB1 = fmaf(bvv, wk2, kB1);
            vA1 = fmaf(av, wv2, vA1); vB1 = fmaf(bvv, wv2, vB1);
        }
    }
    g_q[gA * 36 + j] = qA0; g_q[gB * 36 + j] = qB0;
    g_k[gA * 36 + j] = kA0; g_k[gB * 36 + j] = kB0;
    g_v[gA * 36 + j] = vA0; g_v[gB * 36 + j] = vB0;
    if (e2) {
        g_q[gA * 36 + j2] = qA1; g_q[gB * 36 + j2] = qB1;
        g_k[gA * 36 + j2] = kA1; g_k[gB * 36 + j2] = kB1;
        g_v[gA * 36 + j2] = vA1; g_v[gB * 36 + j2] = vB1;
    }
}

// =============================================================
// Fused row chain (R10 v1): 512 threads = 16 warps = 32 rows
// =============================================================
#define RC_WO   0
#define RC_W1   1296
#define RC_W2   6480
#define RC_WQ   11664
#define RC_WK   12960
#define RC_WV   14256
#define RC_BO   15552
#define RC_L2G  15588
#define RC_L2B  15624
#define RC_B2   15660
#define RC_B1   15696
#define RC_L1G  15840
#define RC_L1B  15876
#define RC_BQ   15912
#define RC_BK   15948
#define RC_BV   15984
#define RC_YB   16020
#define RC_GB   (16020 + 32*40)
#define RC_TOT  (RC_GB + 32*144)

__global__ void __launch_bounds__(512, 2) rowchain_kernel(
    int4 layer4, int4 next4,
    const float* __restrict__ Wo, const float* __restrict__ bo,
    const float* __restrict__ ln2_g, const float* __restrict__ ln2_b,
    const float* __restrict__ W1, const float* __restrict__ b1,
    const float* __restrict__ W2, const float* __restrict__ b2,
    const float* __restrict__ ln1_g, const float* __restrict__ ln1_b,
    const float* __restrict__ Wq, const float* __restrict__ bq,
    const float* __restrict__ Wk, const float* __restrict__ bk,
    const float* __restrict__ Wv, const float* __restrict__ bv)
{
    extern __shared__ float sm[];
    int tid = threadIdx.x, lane = tid & 31, w = tid >> 5;
    int s = blockIdx.z;
    int L = pick4(layer4, s);
    int Ln = pick4(next4, s);

    cp4(sm + RC_WO, Wo + L * 1296, 1296, tid, 512);
    cp4(sm + RC_W1, W1 + L * 5184, 5184, tid, 512);
    cp4(sm + RC_W2, W2 + L * 5184, 5184, tid, 512);
    cp4(sm + RC_BO, bo + L * 36, 36, tid, 512);
    cp4(sm + RC_L2G, ln2_g + L * 36, 36, tid, 512);
    cp4(sm + RC_L2B, ln2_b + L * 36, 36, tid, 512);
    cp4(sm + RC_B2, b2 + L * 36, 36, tid, 512);
    cp4(sm + RC_B1, b1 + L * 144, 144, tid, 512);
    if (Ln >= 0) {
        cp4(sm + RC_WQ, Wq + Ln * 1296, 1296, tid, 512);
        cp4(sm + RC_WK, Wk + Ln * 1296, 1296, tid, 512);
        cp4(sm + RC_WV, Wv + Ln * 1296, 1296, tid, 512);
        cp4(sm + RC_L1G, ln1_g + Ln * 36, 36, tid, 512);
        cp4(sm + RC_L1B, ln1_b + Ln * 36, 36, tid, 512);
        cp4(sm + RC_BQ, bq + Ln * 36, 36, tid, 512);
        cp4(sm + RC_BK, bk + Ln * 36, 36, tid, 512);
        cp4(sm + RC_BV, bv + Ln * 36, 36, tid, 512);
    }
    __syncthreads();

    int rA = blockIdx.x * 32 + w * 2;
    int gA = s * 2400 + rA, gB = gA + 1;
    int j = lane, j2 = lane + 32;
    bool e2 = lane < 4;
    bool e16 = lane < 16;
    float* bufA = sm + RC_YB + (w * 2) * 40;
    float* bufB = bufA + 40;
    float* gbA  = sm + RC_GB + (w * 2) * 144;
    float* gbB  = gbA + 144;

    bufA[lane] = g_o[gA * 36 + lane];
    bufB[lane] = g_o[gB * 36 + lane];
    if (e2) { bufA[j2] = g_o[gA * 36 + j2]; bufB[j2] = g_o[gB * 36 + j2]; }
    __syncwarp();

    float zA0 = g_z[gA * 36 + j], zB0 = g_z[gB * 36 + j];
    float zA1 = e2 ? g_z[gA * 36 + j2] : 0.f;
    float zB1 = e2 ? g_z[gB * 36 + j2] : 0.f;

    float tA0 = sm[RC_BO + j], tB0 = tA0;
    float tA1 = 0.f, tB1 = 0.f;
    if (e2) { tA1 = sm[RC_BO + j2]; tB1 = tA1; }
#pragma unroll
    for (int d = 0; d < 36; d++) {
        float av = bufA[d], bvv = bufB[d];
        float wv = sm[RC_WO + d * 36 + j];
        tA0 = fmaf(av, wv, tA0);
        tB0 = fmaf(bvv, wv, tB0);
        if (e2) {
            float wv2 = sm[RC_WO + d * 36 + j2];
            tA1 = fmaf(av, wv2, tA1);
            tB1 = fmaf(bvv, wv2, tB1);
        }
    }
    tA0 += zA0; tB0 += zB0; tA1 += zA1; tB1 += zB1;

    {
        float sA = wred(tA0 + (e2 ? tA1 : 0.f));
        float qA = wred(tA0 * tA0 + (e2 ? tA1 * tA1 : 0.f));
        float sB = wred(tB0 + (e2 ? tB1 : 0.f));
        float qB = wred(tB0 * tB0 + (e2 ? tB1 * tB1 : 0.f));
        float mA = sA * (1.f / 36.f), mB = sB * (1.f / 36.f);
        float rsA = rsqrtf(qA * (1.f / 36.f) - mA * mA + 1e-6f);
        float rsB = rsqrtf(qB * (1.f / 36.f) - mB * mB + 1e-6f);
        bufA[j] = sm[RC_L2G + j] * (tA0 - mA) * rsA + sm[RC_L2B + j];
        bufB[j] = sm[RC_L2G + j] * (tB0 - mB) * rsB + sm[RC_L2B + j];
        if (e2) {
            bufA[j2] = sm[RC_L2G + j2] * (tA1 - mA) * rsA + sm[RC_L2B + j2];
            bufB[j2] = sm[RC_L2G + j2] * (tB1 - mB) * rsB + sm[RC_L2B + j2];
        }
    }
    __syncwarp();

    {
        float fA[5], fB[5];
#pragma unroll
        for (int k = 0; k < 4; k++) {
            fA[k] = sm[RC_B1 + lane + 32 * k];
            fB[k] = fA[k];
        }
        fA[4] = e16 ? sm[RC_B1 + 128 + lane] : 0.f;
        fB[4] = fA[4];
#pragma unroll
        for (int d = 0; d < 36; d++) {
            float va = bufA[d], vb = bufB[d];
#pragma unroll
            for (int k = 0; k < 4; k++) {
                float wv = sm[RC_W1 + d * 144 + lane + 32 * k];
                fA[k] = fmaf(va, wv, fA[k]);
                fB[k] = fmaf(vb, wv, fB[k]);
            }
            if (e16) {
                float wv = sm[RC_W1 + d * 144 + 128 + lane];
                fA[4] = fmaf(va, wv, fA[4]);
                fB[4] = fmaf(vb, wv, fB[4]);
            }
        }
#pragma unroll
        for (int k = 0; k < 4; k++) {
            gbA[lane + 32 * k] = gelu(fA[k]);
            gbB[lane + 32 * k] = gelu(fB[k]);
        }
        if (e16) {
            gbA[128 + lane] = gelu(fA[4]);
            gbB[128 + lane] = gelu(fB[4]);
        }
    }
    __syncwarp();

    float znA0, znB0, znA1 = 0.f, znB1 = 0.f;
    {
        float oA0 = sm[RC_B2 + j], oB0 = oA0;
        float oA1 = 0.f, oB1 = 0.f;
        if (e2) { oA1 = sm[RC_B2 + j2]; oB1 = oA1; }
#pragma unroll 6
        for (int d = 0; d < 144; d++) {
            float ga = gbA[d], gb = gbB[d];
            float wv = sm[RC_W2 + d * 36 + j];
            oA0 = fmaf(ga, wv, oA0);
            oB0 = fmaf(gb, wv, oB0);
            if (e2) {
                float wv2 = sm[RC_W2 + d * 36 + j2];
                oA1 = fmaf(ga, wv2, oA1);
                oB1 = fmaf(gb, wv2, oB1);
            }
        }
        znA0 = oA0 + tA0; znB0 = oB0 + tB0;
        znA1 = oA1 + tA1; znB1 = oB1 + tB1;
    }
    g_z[gA * 36 + j] = znA0;
    g_z[gB * 36 + j] = znB0;
    if (e2) { g_z[gA * 36 + j2] = znA1; g_z[gB * 36 + j2] = znB1; }

    if (Ln < 0) return;

    {
        float sA = wred(znA0 + (e2 ? znA1 : 0.f));
        float qA = wred(znA0 * znA0 + (e2 ? znA1 * znA1 : 0.f));
        float sB = wred(znB0 + (e2 ? znB1 : 0.f));
        float qB = wred(znB0 * znB0 + (e2 ? znB1 * znB1 : 0.f));
        float mA = sA * (1.f / 36.f), mB = sB * (1.f / 36.f);
        float rsA = rsqrtf(qA * (1.f / 36.f) - mA * mA + 1e-6f);
        float rsB = rsqrtf(qB * (1.f / 36.f) - mB * mB + 1e-6f);
        bufA[j] = sm[RC_L1G + j] * (znA0 - mA) * rsA + sm[RC_L1B + j];
        bufB[j] = sm[RC_L1G + j] * (znB0 - mB) * rsB + sm[RC_L1B + j];
        if (e2) {
            bufA[j2] = sm[RC_L1G + j2] * (znA1 - mA) * rsA + sm[RC_L1B + j2];
            bufB[j2] = sm[RC_L1G + j2] * (znB1 - mB) * rsB + sm[RC_L1B + j2];
        }
    }
    __syncwarp();

    {
        float qA0 = sm[RC_BQ + j], qB0 = qA0;
        float kA0 = sm[RC_BK + j], kB0 = kA0;
        float vA0 = sm[RC_BV + j], vB0 = vA0;
        float qA1 = 0.f, qB1 = 0.f, kA1 = 0.f, kB1 = 0.f, vA1 = 0.f, vB1 = 0.f;
        if (e2) {
            qA1 = sm[RC_BQ + j2]; qB1 = qA1;
            kA1 = sm[RC_BK + j2]; kB1 = kA1;
            vA1 = sm[RC_BV + j2]; vB1 = vA1;
        }
#pragma unroll
        for (int d = 0; d < 36; d++) {
            float av = bufA[d], bvv = bufB[d];
            float wq = sm[RC_WQ + d * 36 + j];
            float wk = sm[RC_WK + d * 36 + j];
            float wv = sm[RC_WV + d * 36 + j];
            qA0 = fmaf(av, wq, qA0); qB0 = fmaf(bvv, wq, qB0);
            kA0 = fmaf(av, wk, kA0); kB0 = fmaf(bvv, wk, kB0);
            vA0 = fmaf(av, wv, vA0); vB0 = fmaf(bvv, wv, vB0);
            if (e2) {
                float wq2 = sm[RC_WQ + d * 36 + j2];
                float wk2 = sm[RC_WK + d * 36 + j2];
                float wv2 = sm[RC_WV + d * 36 + j2];
                qA1 = fmaf(av, wq2, qA1); qB1 = fmaf(bvv, wq2, qB1);
                kA1 = fmaf(av, wk2, kA1); kB1 = fmaf(bvv, wk2, kB1);
                vA1 = fmaf(av, wv2, vA1); vB1 = fmaf(bvv, wv2, vB1);
            }
        }
        g_q[gA * 36 + j] = qA0; g_q[gB * 36 + j] = qB0;
        g_k[gA * 36 + j] = kA0; g_k[gB * 36 + j] = kB0;
        g_v[gA * 36 + j] = vA0; g_v[gB * 36 + j] = vB0;
        if (e2) {
            g_q[gA * 36 + j2] = qA1; g_q[gB * 36 + j2] = qB1;
            g_k[gA * 36 + j2] = kA1; g_k[gB * 36 + j2] = kB1;
            g_v[gA * 36 + j2] = vA1; g_v[gB * 36 + j2] = vB1;
        }
    }
}

// =============================================================
// attention: fp32 smem, hybrid per-head scheme
//   h<=3: two-pass (score array) for max NQ
//   h>=4: online softmax with retuned NQ
// =============================================================
template<int DK, int NQ>
__device__ __forceinline__ void attn_hg_online(
    const float* __restrict__ ksh, const float* __restrict__ vsh,
    const float* __restrict__ qsh, float* __restrict__ ob,
    int q0, int g, int off, int lane)
{
    float qreg[NQ][DK];
#pragma unroll
    for (int qq = 0; qq < NQ; qq++) {
        int ql = g * NQ + qq;
#pragma unroll
        for (int d = 0; d < DK; d++)
            qreg[qq][d] = (ql < QT) ? qsh[ql * 36 + off + d] : 0.f;
    }
    float acc[NQ][DK];
    float ssum[NQ];
#pragma unroll
    for (int qq = 0; qq < NQ; qq++) {
        ssum[qq] = 0.f;
#pragma unroll
        for (int d = 0; d < DK; d++) acc[qq][d] = 0.f;
    }
    const float scale2 = rsqrtf((float)DK) * 1.44269504088896f;
    for (int i = 0; i < NI; i++) {
        int m = i * 32 + lane;
        if (m < LSEQ) {
            const float* kr = ksh + m * KVP + off;
            const float* vr = vsh + m * KVP + off;
            float p[NQ];
#pragma unroll
            for (int qq = 0; qq < NQ; qq++) p[qq] = 0.f;
#pragma unroll
            for (int d = 0; d < DK; d++) {
                float kv = kr[d];
#pragma unroll
                for (int qq = 0; qq < NQ; qq++)
                    p[qq] = fmaf(qreg[qq][d], kv, p[qq]);
            }
#pragma unroll
            for (int qq = 0; qq < NQ; qq++) {
                p[qq] = ex2(p[qq] * scale2);
                ssum[qq] += p[qq];
            }
#pragma unroll
            for (int d = 0; d < DK; d++) {
                float vv = vr[d];
#pragma unroll
                for (int qq = 0; qq < NQ; qq++)
                    acc[qq][d] = fmaf(p[qq], vv, acc[qq][d]);
            }
        }
    }
    float inv[NQ];
#pragma unroll
    for (int qq = 0; qq < NQ; qq++) inv[qq] = 1.f / wred(ssum[qq]);
#pragma unroll
    for (int qq = 0; qq < NQ; qq++) {
        int ql = g * NQ + qq;
#pragma unroll
        for (int d = 0; d < DK; d++) {
            float a = wred(acc[qq][d]);
            if (ql < QT && lane == ((qq * DK + d) & 31))
                ob[(q0 + ql) * 36 + off + d] = a * inv[qq];
        }
    }
}

template<int DK, int NQ>
__device__ __forceinline__ void attn_hg_2pass(
    const float* __restrict__ ksh, const float* __restrict__ vsh,
    const float* __restrict__ qsh, float* __restrict__ ob,
    int q0, int g, int off, int lane)
{
    float sc[NQ][NI];
    float ssum[NQ];
    const float scale2 = rsqrtf((float)DK) * 1.44269504088896f;
    {
        float qreg[NQ][DK];
#pragma unroll
        for (int qq = 0; qq < NQ; qq++) {
            int ql = g * NQ + qq;
#pragma unroll
            for (int d = 0; d < DK; d++)
                qreg[qq][d] = (ql < QT) ? qsh[ql * 36 + off + d] : 0.f;
        }
#pragma unroll
        for (int qq = 0; qq < NQ; qq++) ssum[qq] = 0.f;
        for (int i = 0; i < NI; i++) {
            int m = i * 32 + lane;
            if (m < LSEQ) {
                const float* kr = ksh + m * KVP + off;
                float p[NQ];
#pragma unroll
                for (int qq = 0; qq < NQ; qq++) p[qq] = 0.f;
#pragma unroll
                for (int d = 0; d < DK; d++) {
                    float kv = kr[d];
#pragma unroll
                    for (int qq = 0; qq < NQ; qq++)
                        p[qq] = fmaf(qreg[qq][d], kv, p[qq]);
                }
#pragma unroll
                for (int qq = 0; qq < NQ; qq++) {
                    float e = ex2(p[qq] * scale2);
                    sc[qq][i] = e;
                    ssum[qq] += e;
                }
            } else {
#pragma unroll
                for (int qq = 0; qq < NQ; qq++) sc[qq][i] = 0.f;
            }
        }
    }
    float inv[NQ];
#pragma unroll
    for (int qq = 0; qq < NQ; qq++) inv[qq] = 1.f / wred(ssum[qq]);

    float acc[NQ][DK];
#pragma unroll
    for (int qq = 0; qq < NQ; qq++)
#pragma unroll
        for (int d = 0; d < DK; d++) acc[qq][d] = 0.f;
    for (int i = 0; i < NI; i++) {
        int m = i * 32 + lane;
        if (m < LSEQ) {
            const float* vr = vsh + m * KVP + off;
#pragma unroll
            for (int d = 0; d < DK; d++) {
                float vv = vr[d];
#pragma unroll
                for (int qq = 0; qq < NQ; qq++)
                    acc[qq][d] = fmaf(sc[qq][i], vv, acc[qq][d]);
            }
        }
    }
#pragma unroll
    for (int qq = 0; qq < NQ; qq++) {
        int ql = g * NQ + qq;
#pragma unroll
        for (int d = 0; d < DK; d++) {
            float a = wred(acc[qq][d]);
            if (ql < QT && lane == ((qq * DK + d) & 31))
                ob[(q0 + ql) * 36 + off + d] = a * inv[qq];
        }
    }
}

template<int DK, int NQ, bool TWOPASS>
__device__ void attn_run(const float* ksh, const float* vsh, const float* qsh,
                         float* ob, int q0, int lane, int wid)
{
    constexpr int H  = 36 / DK;
    constexpr int NG = (QT + NQ - 1) / NQ;
    for (int u = wid; u < H * NG; u += NWARP) {
        int hh = u / NG, g = u % NG;
        if (TWOPASS)
            attn_hg_2pass<DK, NQ>(ksh, vsh, qsh, ob, q0, g, hh * DK, lane);
        else
            attn_hg_online<DK, NQ>(ksh, vsh, qsh, ob, q0, g, hh * DK, lane);
    }
}

__global__ void __launch_bounds__(512, 1) attn_kernel(int4 heads4)
{
    extern __shared__ float sh[];
    float* ksh = sh;
    float* vsh = sh + 600 * KVP;
    float* qsh = sh + 1200 * KVP;
    int tile = blockIdx.x, b = blockIdx.y, s = blockIdx.z;
    int h = pick4(heads4, s);
    int base = (s * 4 + b) * 21600;

    const float4* kg = (const float4*)(g_k + base);
    const float4* vg = (const float4*)(g_v + base);
    for (int i4 = threadIdx.x; i4 < 5400; i4 += 512) {
        int row = i4 / 9, c = (i4 % 9) * 4;
        float4 kv = kg[i4], vv = vg[i4];
        float* kd = ksh + row * KVP + c;
        kd[0] = kv.x; kd[1] = kv.y; kd[2] = kv.z; kd[3] = kv.w;
        float* vd = vsh + row * KVP + c;
        vd[0] = vv.x; vd[1] = vv.y; vd[2] = vv.z; vd[3] = vv.w;
    }
    int q0 = tile * QT;
    for (int i = threadIdx.x; i < QT * 36; i += 512) qsh[i] = g_q[base + q0 * 36 + i];
    __syncthreads();

    int lane = threadIdx.x & 31, wid = threadIdx.x >> 5;
    float* ob = g_o + base;
    switch (h) {
        case 1:  attn_run<36, 2, true >(ksh, vsh, qsh, ob, q0, lane, wid); break;
        case 2:  attn_run<18, 3, true >(ksh, vsh, qsh, ob, q0, lane, wid); break;
        case 3:  attn_run<12, 3, true >(ksh, vsh, qsh, ob, q0, lane, wid); break;
        case 4:  attn_run<9,  5, false>(ksh, vsh, qsh, ob, q0, lane, wid); break;
        case 6:  attn_run<6,  6, false>(ksh, vsh, qsh, ob, q0, lane, wid); break;
        case 9:  attn_run<4, 10, false>(ksh, vsh, qsh, ob, q0, lane, wid); break;
        case 12: attn_run<3, 10, false>(ksh, vsh, qsh, ob, q0, lane, wid); break;
        case 18: attn_run<2, 15, false>(ksh, vsh, qsh, ob, q0, lane, wid); break;
        case 36: attn_run<1, 15, false>(ksh, vsh, qsh, ob, q0, lane, wid); break;
    }
}

// ---------------- SE gate ----------------
__global__ void __launch_bounds__(288) gate_kernel()
{
    int sb = blockIdx.x;
    __shared__ float red[288];
    int t = threadIdx.x;
    int c = t / 8, k = t % 8;
    float sum = 0.f;
    const float* zz = g_z + sb * 21600;
    for (int l = k; l < 600; l += 8) sum += zz[l * 36 + c];
    red[t] = sum;
    __syncthreads();
    if (k == 0) {
        float tot = 0.f;
#pragma unroll
        for (int i = 0; i < 8; i++) tot += red[c * 8 + i];
        float mean = tot * (1.f / 600.f);
        g_gate[sb * 36 + c] = 1.f / (1.f + __expf(-mean));
    }
}

// ---------------- conv + BN + ReLU ----------------
__global__ void __launch_bounds__(360) conv_kernel(
    const float* __restrict__ conv_w, const float* __restrict__ conv_b,
    const float* __restrict__ bn_g, const float* __restrict__ bn_b,
    const float* __restrict__ bn_mean, const float* __restrict__ bn_var,
    float* __restrict__ out)
{
    extern __shared__ float esh[];
    float* xf  = esh;
    float* wsh = esh + 144 * 32;
    int b = blockIdx.y, lbase = blockIdx.x * 30;
    int t = threadIdx.x;

    for (int idx = t; idx < 144 * 32; idx += 360) {
        int i = idx >> 5, lc = idx & 31;
        int l = lbase + lc - 1;
        float val = 0.f;
        if (l >= 0 && l < 600) {
            int s = i / 36, c = i % 36;
            val = g_gate[(s * 4 + b) * 36 + c] * g_z[((s * 4 + b) * 600 + l) * 36 + c];
        }
        xf[i * 32 + lc] = val;
    }
    for (int idx = t; idx < 36 * 432; idx += 360) {
        int o = idx / 432, rest = idx % 432;
        wsh[o * 433 + rest] = conv_w[idx];
    }
    __syncthreads();

    int o = t % 36, lj = t / 36;
    float scale = bn_g[o] * rsqrtf(bn_var[o] + 1e-5f);
    float shift = bn_b[o] - scale * bn_mean[o];
    float cb = conv_b[o];
    const float* w = wsh + o * 433;
#pragma unroll
    for (int rep = 0; rep < 3; rep++) {
        int lc = lj + rep * 10;
        float acc = cb;
#pragma unroll 8
        for (int i = 0; i < 144; i++) {
            float x0 = xf[i * 32 + lc];
            float x1 = xf[i * 32 + lc + 1];
            float x2 = xf[i * 32 + lc + 2];
            acc += x0 * w[i * 3 + 0] + x1 * w[i * 3 + 1] + x2 * w[i * 3 + 2];
        }
        float y = scale * acc + shift;
        out[b * 21600 + o * 600 + lbase + lc] = fmaxf(y, 0.f);
    }
}

// ---------------- host driver ----------------
extern "C" void kernel_launch(void* const* d_in, const int* in_sizes, int n_in,
                              void* d_out, int out_size)
{
    (void)in_sizes; (void)n_in; (void)out_size;
    const float* x     = (const float*)d_in[0];
    const float* ln1_g = (const float*)d_in[1];
    const float* ln1_b = (const float*)d_in[2];
    const float* Wq    = (const float*)d_in[3];
    const float* bq    = (const float*)d_in[4];
    const float* Wk    = (const float*)d_in[5];
    const float* bk    = (const float*)d_in[6];
    const float* Wv    = (const float*)d_in[7];
    const float* bv    = (const float*)d_in[8];
    const float* Wo    = (const float*)d_in[9];
    const float* bo    = (const float*)d_in[10];
    const float* ln2_g = (const float*)d_in[11];
    const float* ln2_b = (const float*)d_in[12];
    const float* W1    = (const float*)d_in[13];
    const float* b1    = (const float*)d_in[14];
    const float* W2    = (const float*)d_in[15];
    const float* b2    = (const float*)d_in[16];
    const float* conv_w = (const float*)d_in[17];
    const float* conv_b = (const float*)d_in[18];
    const float* bn_g   = (const float*)d_in[19];
    const float* bn_b   = (const float*)d_in[20];
    const float* bn_mean = (const float*)d_in[21];
    const float* bn_var  = (const float*)d_in[22];
    float* out = (float*)d_out;

    static const int HEADS_H[24] = {1,2,3,4,6,9,12,18,36,
                                    1,2,3,4,6,
                                    6,9,12,18,36,
                                    3,4,6,9,12};
    static const int START[4] = {0, 9, 14, 19};
    static const int DEPTH[4] = {9, 5, 5, 5};

    const int ATTN_SMEM = (1200 * KVP + QT * 36) * 4;
    const int CONV_SMEM = (144 * 32 + 36 * 433) * 4;
    const int RC_SMEM   = RC_TOT * 4;
    const int LQ_SMEM   = LQ_TOT * 4;
    cudaFuncSetAttribute(attn_kernel, cudaFuncAttributeMaxDynamicSharedMemorySize, ATTN_SMEM);
    cudaFuncSetAttribute(conv_kernel, cudaFuncAttributeMaxDynamicSharedMemorySize, CONV_SMEM);
    cudaFuncSetAttribute(rowchain_kernel, cudaFuncAttributeMaxDynamicSharedMemorySize, RC_SMEM);
    cudaFuncSetAttribute(lnqkv2_kernel, cudaFuncAttributeMaxDynamicSharedMemorySize, LQ_SMEM);

    int4 L0 = make_int4(0, 9, 14, 19);
    lnqkv2_kernel<<<dim3(75, 1, 4), 512, LQ_SMEM>>>(L0, x, ln1_g, ln1_b,
                                                    Wq, bq, Wk, bk, Wv, bv);

    for (int t = 0; t < 9; t++) {
        int nA = (t < 5) ? 4 : 1;
        int lc[4], nx[4], hh[4];
        for (int s = 0; s < 4; s++) {
            int L = START[s] + t;
            lc[s] = (L < 24) ? L : 0;
            hh[s] = (t < DEPTH[s]) ? HEADS_H[lc[s]] : 1;
            nx[s] = (t + 1 < DEPTH[s]) ? lc[s] + 1 : -1;
        }
        int4 Lc = make_int4(lc[0], lc[1], lc[2], lc[3]);
        int4 Nx = make_int4(nx[0], nx[1], nx[2], nx[3]);
        int4 Hh = make_int4(hh[0], hh[1], hh[2], hh[3]);

        attn_kernel<<<dim3(NTILES, 4, nA), 512, ATTN_SMEM>>>(Hh);
        rowchain_kernel<<<dim3(75, 1, nA), 512, RC_SMEM>>>(
            Lc, Nx, Wo, bo, ln2_g, ln2_b, W1, b1, W2, b2,
            ln1_g, ln1_b, Wq, bq, Wk, bk, Wv, bv);
    }

    gate_kernel<<<16, 288>>>();
    conv_kernel<<<dim3(20, 4), 360, CONV_SMEM>>>(conv_w, conv_b, bn_g, bn_b,
                                                 bn_mean, bn_var, out);
}

// round 15
// speedup vs baseline: 1.0753x; 1.0179x over previous
#include <cuda_runtime.h>
#include <math.h>

#define NSTACK 4
#define BATCH  4
#define LSEQ   600
#define DMODEL 36
#define DFF    144
#define QT     30
#define NTILES 20
#define KH     300   // keys per half
#define NI2    10    // ceil(300/32)
#define KVP    37
#define NWARP  10

// ---------------- scratch ----------------
__device__ float g_z[NSTACK*BATCH*LSEQ*DMODEL];
__device__ float g_q[NSTACK*BATCH*LSEQ*DMODEL];
__device__ float g_k[NSTACK*BATCH*LSEQ*DMODEL];
__device__ float g_v[NSTACK*BATCH*LSEQ*DMODEL];
__device__ float g_o0[NSTACK*BATCH*LSEQ*DMODEL];
__device__ float g_o1[NSTACK*BATCH*LSEQ*DMODEL];
__device__ float g_s0[NSTACK*BATCH*LSEQ*DMODEL];
__device__ float g_s1[NSTACK*BATCH*LSEQ*DMODEL];
__device__ float g_gate[NSTACK*BATCH*DMODEL];

__device__ __forceinline__ int pick4(int4 v, int s) {
    return (s == 0) ? v.x : (s == 1) ? v.y : (s == 2) ? v.z : v.w;
}
__device__ __forceinline__ float wred(float v) {
#pragma unroll
    for (int o = 16; o > 0; o >>= 1) v += __shfl_xor_sync(0xffffffffu, v, o);
    return v;
}
__device__ __forceinline__ float ex2(float x) {
    float r;
    asm("ex2.approx.f32 %0, %1;" : "=f"(r) : "f"(x));
    return r;
}
__device__ __forceinline__ float gelu(float u) {
    float a = 1.5957691216057308f * (u + 0.044715f * u * u * u);
    return __fdividef(u, 1.f + __expf(-a));
}
__device__ __forceinline__ void cp4(float* dst, const float* __restrict__ src,
                                    int n, int tid, int nt) {
    const float4* s4 = (const float4*)src;
    float4* d4 = (float4*)dst;
    for (int i = tid; i < (n >> 2); i += nt) d4[i] = s4[i];
}
__device__ __forceinline__ float pe_val(int l, int d) {
    int de = d & ~1;
    float freq = __expf(-0.25584278811044947f * (float)de);
    float ang = (float)l * freq;
    return (d & 1) ? cosf(ang) : sinf(ang);
}

// =============================================================
// Initial LN1 + QKV with fused embedding (x^T + PE -> g_z)
// =============================================================
#define LQ_WQ 0
#define LQ_WK 1296
#define LQ_WV 2592
#define LQ_LG 3888
#define LQ_LB 3924
#define LQ_BQ 3960
#define LQ_BK 3996
#define LQ_BV 4032
#define LQ_YB 4068
#define LQ_TOT (4068 + 32*40)

__global__ void __launch_bounds__(512, 2) lnqkv2_kernel(
    int4 layer4, const float* __restrict__ x,
    const float* __restrict__ ln1_g, const float* __restrict__ ln1_b,
    const float* __restrict__ Wq, const float* __restrict__ bq,
    const float* __restrict__ Wk, const float* __restrict__ bk,
    const float* __restrict__ Wv, const float* __restrict__ bv)
{
    extern __shared__ float sm[];
    int tid = threadIdx.x, lane = tid & 31, w = tid >> 5;
    int s = blockIdx.z;
    int L = pick4(layer4, s);

    cp4(sm + LQ_WQ, Wq + L * 1296, 1296, tid, 512);
    cp4(sm + LQ_WK, Wk + L * 1296, 1296, tid, 512);
    cp4(sm + LQ_WV, Wv + L * 1296, 1296, tid, 512);
    cp4(sm + LQ_LG, ln1_g + L * 36, 36, tid, 512);
    cp4(sm + LQ_LB, ln1_b + L * 36, 36, tid, 512);
    cp4(sm + LQ_BQ, bq + L * 36, 36, tid, 512);
    cp4(sm + LQ_BK, bk + L * 36, 36, tid, 512);
    cp4(sm + LQ_BV, bv + L * 36, 36, tid, 512);
    __syncthreads();

    int rA = blockIdx.x * 32 + w * 2;
    int gA = s * 2400 + rA, gB = gA + 1;
    int j = lane, j2 = lane + 32;
    bool e2 = lane < 4;
    float* bufA = sm + LQ_YB + (w * 2) * 40;
    float* bufB = bufA + 40;

    {
        int bA = rA / 600, lA = rA - bA * 600;
        int rB = rA + 1;
        int bB = rB / 600, lB = rB - bB * 600;
        float za = x[bA * 21600 + lane * 600 + lA] + pe_val(lA, lane);
        float zb = x[bB * 21600 + lane * 600 + lB] + pe_val(lB, lane);
        bufA[lane] = za; g_z[gA * 36 + lane] = za;
        bufB[lane] = zb; g_z[gB * 36 + lane] = zb;
        if (e2) {
            float za2 = x[bA * 21600 + j2 * 600 + lA] + pe_val(lA, j2);
            float zb2 = x[bB * 21600 + j2 * 600 + lB] + pe_val(lB, j2);
            bufA[j2] = za2; g_z[gA * 36 + j2] = za2;
            bufB[j2] = zb2; g_z[gB * 36 + j2] = zb2;
        }
    }
    __syncwarp();

    float tA0 = bufA[j], tB0 = bufB[j];
    float tA1 = e2 ? bufA[j2] : 0.f, tB1 = e2 ? bufB[j2] : 0.f;
    float sA = wred(tA0 + (e2 ? tA1 : 0.f));
    float qA = wred(tA0 * tA0 + (e2 ? tA1 * tA1 : 0.f));
    float sB = wred(tB0 + (e2 ? tB1 : 0.f));
    float qB = wred(tB0 * tB0 + (e2 ? tB1 * tB1 : 0.f));
    float mA = sA * (1.f / 36.f), mB = sB * (1.f / 36.f);
    float rsA = rsqrtf(qA * (1.f / 36.f) - mA * mA + 1e-6f);
    float rsB = rsqrtf(qB * (1.f / 36.f) - mB * mB + 1e-6f);

    bufA[j] = sm[LQ_LG + j] * (tA0 - mA) * rsA + sm[LQ_LB + j];
    bufB[j] = sm[LQ_LG + j] * (tB0 - mB) * rsB + sm[LQ_LB + j];
    if (e2) {
        bufA[j2] = sm[LQ_LG + j2] * (tA1 - mA) * rsA + sm[LQ_LB + j2];
        bufB[j2] = sm[LQ_LG + j2] * (tB1 - mB) * rsB + sm[LQ_LB + j2];
    }
    __syncwarp();

    float qA0 = sm[LQ_BQ + j], qB0 = qA0;
    float kA0 = sm[LQ_BK + j], kB0 = kA0;
    float vA0 = sm[LQ_BV + j], vB0 = vA0;
    float qA1 = 0.f, qB1 = 0.f, kA1 = 0.f, kB1 = 0.f, vA1 = 0.f, vB1 = 0.f;
    if (e2) {
        qA1 = sm[LQ_BQ + j2]; qB1 = qA1;
        kA1 = sm[LQ_BK + j2]; kB1 = kA1;
        vA1 = sm[LQ_BV + j2]; vB1 = vA1;
    }
#pragma unroll
    for (int d = 0; d < 36; d++) {
        float av = bufA[d], bvv = bufB[d];
        float wq = sm[LQ_WQ + d * 36 + j];
        float wk = sm[LQ_WK + d * 36 + j];
        float wv = sm[LQ_WV + d * 36 + j];
        qA0 = fmaf(av, wq, qA0); qB0 = fmaf(bvv, wq, qB0);
        kA0 = fmaf(av, wk, kA0); kB0 = fmaf(bvv, wk, kB0);
        vA0 = fmaf(av, wv, vA0); vB0 = fmaf(bvv, wv, vB0);
        if (e2) {
            float wq2 = sm[LQ_WQ + d * 36 + j2];
            float wk2 = sm[LQ_WK + d * 36 + j2];
            float wv2 = sm[LQ_WV + d * 36 + j2];
            qA1 = fmaf(av, wq2, qA1); qB1 = fmaf(bvv, wq2, qB1);
            kA1 = fmaf(av, wk2, kA1); kB1 = fmaf(bvv, wk2, kB1);
            vA1 = fmaf(av, wv2, vA1); vB1 = fmaf(bvv, wv2, vB1);
        }
    }
    g_q[gA * 36 + j] = qA0; g_q[gB * 36 + j] = qB0;
    g_k[gA * 36 + j] = kA0; g_k[gB * 36 + j] = kB0;
    g_v[gA * 36 + j] = vA0; g_v[gB * 36 + j] = vB0;
    if (e2) {
        g_q[gA * 36 + j2] = qA1; g_q[gB * 36 + j2] = qB1;
        g_k[gA * 36 + j2] = kA1; g_k[gB * 36 + j2] = kB1;
        g_v[gA * 36 + j2] = vA1; g_v[gB * 36 + j2] = vB1;
    }
}

// =============================================================
// Fused row chain + split-K attention combine in staging
// =============================================================
#define RC_WO   0
#define RC_W1   1296
#define RC_W2   6480
#define RC_WQ   11664
#define RC_WK   12960
#define RC_WV   14256
#define RC_BO   15552
#define RC_L2G  15588
#define RC_L2B  15624
#define RC_B2   15660
#define RC_B1   15696
#define RC_L1G  15840
#define RC_L1B  15876
#define RC_BQ   15912
#define RC_BK   15948
#define RC_BV   15984
#define RC_YB   16020
#define RC_GB   (16020 + 32*40)
#define RC_TOT  (RC_GB + 32*144)

__global__ void __launch_bounds__(512, 2) rowchain_kernel(
    int4 layer4, int4 next4, int4 dk4,
    const float* __restrict__ Wo, const float* __restrict__ bo,
    const float* __restrict__ ln2_g, const float* __restrict__ ln2_b,
    const float* __restrict__ W1, const float* __restrict__ b1,
    const float* __restrict__ W2, const float* __restrict__ b2,
    const float* __restrict__ ln1_g, const float* __restrict__ ln1_b,
    const float* __restrict__ Wq, const float* __restrict__ bq,
    const float* __restrict__ Wk, const float* __restrict__ bk,
    const float* __restrict__ Wv, const float* __restrict__ bv)
{
    extern __shared__ float sm[];
    int tid = threadIdx.x, lane = tid & 31, w = tid >> 5;
    int s = blockIdx.z;
    int L = pick4(layer4, s);
    int Ln = pick4(next4, s);
    int dkc = pick4(dk4, s);

    cp4(sm + RC_WO, Wo + L * 1296, 1296, tid, 512);
    cp4(sm + RC_W1, W1 + L * 5184, 5184, tid, 512);
    cp4(sm + RC_W2, W2 + L * 5184, 5184, tid, 512);
    cp4(sm + RC_BO, bo + L * 36, 36, tid, 512);
    cp4(sm + RC_L2G, ln2_g + L * 36, 36, tid, 512);
    cp4(sm + RC_L2B, ln2_b + L * 36, 36, tid, 512);
    cp4(sm + RC_B2, b2 + L * 36, 36, tid, 512);
    cp4(sm + RC_B1, b1 + L * 144, 144, tid, 512);
    if (Ln >= 0) {
        cp4(sm + RC_WQ, Wq + Ln * 1296, 1296, tid, 512);
        cp4(sm + RC_WK, Wk + Ln * 1296, 1296, tid, 512);
        cp4(sm + RC_WV, Wv + Ln * 1296, 1296, tid, 512);
        cp4(sm + RC_L1G, ln1_g + Ln * 36, 36, tid, 512);
        cp4(sm + RC_L1B, ln1_b + Ln * 36, 36, tid, 512);
        cp4(sm + RC_BQ, bq + Ln * 36, 36, tid, 512);
        cp4(sm + RC_BK, bk + Ln * 36, 36, tid, 512);
        cp4(sm + RC_BV, bv + Ln * 36, 36, tid, 512);
    }
    __syncthreads();

    int rA = blockIdx.x * 32 + w * 2;
    int gA = s * 2400 + rA, gB = gA + 1;
    int j = lane, j2 = lane + 32;
    bool e2 = lane < 4;
    bool e16 = lane < 16;
    float* bufA = sm + RC_YB + (w * 2) * 40;
    float* bufB = bufA + 40;
    float* gbA  = sm + RC_GB + (w * 2) * 144;
    float* gbB  = gbA + 144;

    // stage attention output rows: combine split-K partials
    {
        int hd = lane / dkc;
        float dA = __fdividef(1.f, g_s0[gA * 36 + hd] + g_s1[gA * 36 + hd]);
        float dB = __fdividef(1.f, g_s0[gB * 36 + hd] + g_s1[gB * 36 + hd]);
        bufA[lane] = (g_o0[gA * 36 + lane] + g_o1[gA * 36 + lane]) * dA;
        bufB[lane] = (g_o0[gB * 36 + lane] + g_o1[gB * 36 + lane]) * dB;
        if (e2) {
            int hd2 = j2 / dkc;
            float dA2 = __fdividef(1.f, g_s0[gA * 36 + hd2] + g_s1[gA * 36 + hd2]);
            float dB2 = __fdividef(1.f, g_s0[gB * 36 + hd2] + g_s1[gB * 36 + hd2]);
            bufA[j2] = (g_o0[gA * 36 + j2] + g_o1[gA * 36 + j2]) * dA2;
            bufB[j2] = (g_o0[gB * 36 + j2] + g_o1[gB * 36 + j2]) * dB2;
        }
    }
    __syncwarp();

    float zA0 = g_z[gA * 36 + j], zB0 = g_z[gB * 36 + j];
    float zA1 = e2 ? g_z[gA * 36 + j2] : 0.f;
    float zB1 = e2 ? g_z[gB * 36 + j2] : 0.f;

    float tA0 = sm[RC_BO + j], tB0 = tA0;
    float tA1 = 0.f, tB1 = 0.f;
    if (e2) { tA1 = sm[RC_BO + j2]; tB1 = tA1; }
#pragma unroll
    for (int d = 0; d < 36; d++) {
        float av = bufA[d], bvv = bufB[d];
        float wv = sm[RC_WO + d * 36 + j];
        tA0 = fmaf(av, wv, tA0);
        tB0 = fmaf(bvv, wv, tB0);
        if (e2) {
            float wv2 = sm[RC_WO + d * 36 + j2];
            tA1 = fmaf(av, wv2, tA1);
            tB1 = fmaf(bvv, wv2, tB1);
        }
    }
    tA0 += zA0; tB0 += zB0; tA1 += zA1; tB1 += zB1;

    {
        float sA = wred(tA0 + (e2 ? tA1 : 0.f));
        float qA = wred(tA0 * tA0 + (e2 ? tA1 * tA1 : 0.f));
        float sB = wred(tB0 + (e2 ? tB1 : 0.f));
        float qB = wred(tB0 * tB0 + (e2 ? tB1 * tB1 : 0.f));
        float mA = sA * (1.f / 36.f), mB = sB * (1.f / 36.f);
        float rsA = rsqrtf(qA * (1.f / 36.f) - mA * mA + 1e-6f);
        float rsB = rsqrtf(qB * (1.f / 36.f) - mB * mB + 1e-6f);
        bufA[j] = sm[RC_L2G + j] * (tA0 - mA) * rsA + sm[RC_L2B + j];
        bufB[j] = sm[RC_L2G + j] * (tB0 - mB) * rsB + sm[RC_L2B + j];
        if (e2) {
            bufA[j2] = sm[RC_L2G + j2] * (tA1 - mA) * rsA + sm[RC_L2B + j2];
            bufB[j2] = sm[RC_L2G + j2] * (tB1 - mB) * rsB + sm[RC_L2B + j2];
        }
    }
    __syncwarp();

    {
        float fA[5], fB[5];
#pragma unroll
        for (int k = 0; k < 4; k++) {
            fA[k] = sm[RC_B1 + lane + 32 * k];
            fB[k] = fA[k];
        }
        fA[4] = e16 ? sm[RC_B1 + 128 + lane] : 0.f;
        fB[4] = fA[4];
#pragma unroll
        for (int d = 0; d < 36; d++) {
            float va = bufA[d], vb = bufB[d];
#pragma unroll
            for (int k = 0; k < 4; k++) {
                float wv = sm[RC_W1 + d * 144 + lane + 32 * k];
                fA[k] = fmaf(va, wv, fA[k]);
                fB[k] = fmaf(vb, wv, fB[k]);
            }
            if (e16) {
                float wv = sm[RC_W1 + d * 144 + 128 + lane];
                fA[4] = fmaf(va, wv, fA[4]);
                fB[4] = fmaf(vb, wv, fB[4]);
            }
        }
#pragma unroll
        for (int k = 0; k < 4; k++) {
            gbA[lane + 32 * k] = gelu(fA[k]);
            gbB[lane + 32 * k] = gelu(fB[k]);
        }
        if (e16) {
            gbA[128 + lane] = gelu(fA[4]);
            gbB[128 + lane] = gelu(fB[4]);
        }
    }
    __syncwarp();

    float znA0, znB0, znA1 = 0.f, znB1 = 0.f;
    {
        float oA0 = sm[RC_B2 + j], oB0 = oA0;
        float oA1 = 0.f, oB1 = 0.f;
        if (e2) { oA1 = sm[RC_B2 + j2]; oB1 = oA1; }
#pragma unroll 6
        for (int d = 0; d < 144; d++) {
            float ga = gbA[d], gb = gbB[d];
            float wv = sm[RC_W2 + d * 36 + j];
            oA0 = fmaf(ga, wv, oA0);
            oB0 = fmaf(gb, wv, oB0);
            if (e2) {
                float wv2 = sm[RC_W2 + d * 36 + j2];
                oA1 = fmaf(ga, wv2, oA1);
                oB1 = fmaf(gb, wv2, oB1);
            }
        }
        znA0 = oA0 + tA0; znB0 = oB0 + tB0;
        znA1 = oA1 + tA1; znB1 = oB1 + tB1;
    }
    g_z[gA * 36 + j] = znA0;
    g_z[gB * 36 + j] = znB0;
    if (e2) { g_z[gA * 36 + j2] = znA1; g_z[gB * 36 + j2] = znB1; }

    if (Ln < 0) return;

    {
        float sA = wred(znA0 + (e2 ? znA1 : 0.f));
        float qA = wred(znA0 * znA0 + (e2 ? znA1 * znA1 : 0.f));
        float sB = wred(znB0 + (e2 ? znB1 : 0.f));
        float qB = wred(znB0 * znB0 + (e2 ? znB1 * znB1 : 0.f));
        float mA = sA * (1.f / 36.f), mB = sB * (1.f / 36.f);
        float rsA = rsqrtf(qA * (1.f / 36.f) - mA * mA + 1e-6f);
        float rsB = rsqrtf(qB * (1.f / 36.f) - mB * mB + 1e-6f);
        bufA[j] = sm[RC_L1G + j] * (znA0 - mA) * rsA + sm[RC_L1B + j];
        bufB[j] = sm[RC_L1G + j] * (znB0 - mB) * rsB + sm[RC_L1B + j];
        if (e2) {
            bufA[j2] = sm[RC_L1G + j2] * (znA1 - mA) * rsA + sm[RC_L1B + j2];
            bufB[j2] = sm[RC_L1G + j2] * (znB1 - mB) * rsB + sm[RC_L1B + j2];
        }
    }
    __syncwarp();

    {
        float qA0 = sm[RC_BQ + j], qB0 = qA0;
        float kA0 = sm[RC_BK + j], kB0 = kA0;
        float vA0 = sm[RC_BV + j], vB0 = vA0;
        float qA1 = 0.f, qB1 = 0.f, kA1 = 0.f, kB1 = 0.f, vA1 = 0.f, vB1 = 0.f;
        if (e2) {
            qA1 = sm[RC_BQ + j2]; qB1 = qA1;
            kA1 = sm[RC_BK + j2]; kB1 = kA1;
            vA1 = sm[RC_BV + j2]; vB1 = vA1;
        }
#pragma unroll
        for (int d = 0; d < 36; d++) {
            float av = bufA[d], bvv = bufB[d];
            float wq = sm[RC_WQ + d * 36 + j];
            float wk = sm[RC_WK + d * 36 + j];
            float wv = sm[RC_WV + d * 36 + j];
            qA0 = fmaf(av, wq, qA0); qB0 = fmaf(bvv, wq, qB0);
            kA0 = fmaf(av, wk, kA0); kB0 = fmaf(bvv, wk, kB0);
            vA0 = fmaf(av, wv, vA0); vB0 = fmaf(bvv, wv, vB0);
            if (e2) {
                float wq2 = sm[RC_WQ + d * 36 + j2];
                float wk2 = sm[RC_WK + d * 36 + j2];
                float wv2 = sm[RC_WV + d * 36 + j2];
                qA1 = fmaf(av, wq2, qA1); qB1 = fmaf(bvv, wq2, qB1);
                kA1 = fmaf(av, wk2, kA1); kB1 = fmaf(bvv, wk2, kB1);
                vA1 = fmaf(av, wv2, vA1); vB1 = fmaf(bvv, wv2, vB1);
            }
        }
        g_q[gA * 36 + j] = qA0; g_q[gB * 36 + j] = qB0;
        g_k[gA * 36 + j] = kA0; g_k[gB * 36 + j] = kB0;
        g_v[gA * 36 + j] = vA0; g_v[gB * 36 + j] = vB0;
        if (e2) {
            g_q[gA * 36 + j2] = qA1; g_q[gB * 36 + j2] = qB1;
            g_k[gA * 36 + j2] = kA1; g_k[gB * 36 + j2] = kB1;
            g_v[gA * 36 + j2] = vA1; g_v[gB * 36 + j2] = vB1;
        }
    }
}

// =============================================================
// split-K attention: 300 keys/block, 93.1KB smem, 2 blocks/SM,
// 320 threads; writes raw acc + raw exp-sum (combined later)
// =============================================================
template<int DK, int NQ>
__device__ __forceinline__ void attn_hg_online(
    const float* __restrict__ ksh, const float* __restrict__ vsh,
    const float* __restrict__ qsh, float* __restrict__ ob, float* __restrict__ sb,
    int q0, int g, int off, int lane)
{
    float qreg[NQ][DK];
#pragma unroll
    for (int qq = 0; qq < NQ; qq++) {
        int ql = g * NQ + qq;
#pragma unroll
        for (int d = 0; d < DK; d++)
            qreg[qq][d] = (ql < QT) ? qsh[ql * 36 + off + d] : 0.f;
    }
    float acc[NQ][DK];
    float ssum[NQ];
#pragma unroll
    for (int qq = 0; qq < NQ; qq++) {
        ssum[qq] = 0.f;
#pragma unroll
        for (int d = 0; d < DK; d++) acc[qq][d] = 0.f;
    }
    const float scale2 = rsqrtf((float)DK) * 1.44269504088896f;
    for (int i = 0; i < NI2; i++) {
        int m = i * 32 + lane;
        if (m < KH) {
            const float* kr = ksh + m * KVP + off;
            const float* vr = vsh + m * KVP + off;
            float p[NQ];
#pragma unroll
            for (int qq = 0; qq < NQ; qq++) p[qq] = 0.f;
#pragma unroll
            for (int d = 0; d < DK; d++) {
                float kv = kr[d];
#pragma unroll
                for (int qq = 0; qq < NQ; qq++)
                    p[qq] = fmaf(qreg[qq][d], kv, p[qq]);
            }
#pragma unroll
            for (int qq = 0; qq < NQ; qq++) {
                p[qq] = ex2(p[qq] * scale2);
                ssum[qq] += p[qq];
            }
#pragma unroll
            for (int d = 0; d < DK; d++) {
                float vv = vr[d];
#pragma unroll
                for (int qq = 0; qq < NQ; qq++)
                    acc[qq][d] = fmaf(p[qq], vv, acc[qq][d]);
            }
        }
    }
    int head = off / DK;
#pragma unroll
    for (int qq = 0; qq < NQ; qq++) {
        int ql = g * NQ + qq;
        float sv = wred(ssum[qq]);
        if (ql < QT && lane == 0) sb[(q0 + ql) * 36 + head] = sv;
#pragma unroll
        for (int d = 0; d < DK; d++) {
            float a = wred(acc[qq][d]);
            if (ql < QT && lane == ((qq * DK + d) & 31))
                ob[(q0 + ql) * 36 + off + d] = a;
        }
    }
}

template<int DK, int NQ>
__device__ __forceinline__ void attn_hg_2pass(
    const float* __restrict__ ksh, const float* __restrict__ vsh,
    const float* __restrict__ qsh, float* __restrict__ ob, float* __restrict__ sb,
    int q0, int g, int off, int lane)
{
    float sc[NQ][NI2];
    float ssum[NQ];
    const float scale2 = rsqrtf((float)DK) * 1.44269504088896f;
    {
        float qreg[NQ][DK];
#pragma unroll
        for (int qq = 0; qq < NQ; qq++) {
            int ql = g * NQ + qq;
#pragma unroll
            for (int d = 0; d < DK; d++)
                qreg[qq][d] = (ql < QT) ? qsh[ql * 36 + off + d] : 0.f;
        }
#pragma unroll
        for (int qq = 0; qq < NQ; qq++) ssum[qq] = 0.f;
        for (int i = 0; i < NI2; i++) {
            int m = i * 32 + lane;
            if (m < KH) {
                const float* kr = ksh + m * KVP + off;
                float p[NQ];
#pragma unroll
                for (int qq = 0; qq < NQ; qq++) p[qq] = 0.f;
#pragma unroll
                for (int d = 0; d < DK; d++) {
                    float kv = kr[d];
#pragma unroll
                    for (int qq = 0; qq < NQ; qq++)
                        p[qq] = fmaf(qreg[qq][d], kv, p[qq]);
                }
#pragma unroll
                for (int qq = 0; qq < NQ; qq++) {
                    float e = ex2(p[qq] * scale2);
                    sc[qq][i] = e;
                    ssum[qq] += e;
                }
            } else {
#pragma unroll
                for (int qq = 0; qq < NQ; qq++) sc[qq][i] = 0.f;
            }
        }
    }
    float acc[NQ][DK];
#pragma unroll
    for (int qq = 0; qq < NQ; qq++)
#pragma unroll
        for (int d = 0; d < DK; d++) acc[qq][d] = 0.f;
    for (int i = 0; i < NI2; i++) {
        int m = i * 32 + lane;
        if (m < KH) {
            const float* vr = vsh + m * KVP + off;
#pragma unroll
            for (int d = 0; d < DK; d++) {
                float vv = vr[d];
#pragma unroll
                for (int qq = 0; qq < NQ; qq++)
                    acc[qq][d] = fmaf(sc[qq][i], vv, acc[qq][d]);
            }
        }
    }
    int head = off / DK;
#pragma unroll
    for (int qq = 0; qq < NQ; qq++) {
        int ql = g * NQ + qq;
        float sv = wred(ssum[qq]);
        if (ql < QT && lane == 0) sb[(q0 + ql) * 36 + head] = sv;
#pragma unroll
        for (int d = 0; d < DK; d++) {
            float a = wred(acc[qq][d]);
            if (ql < QT && lane == ((qq * DK + d) & 31))
                ob[(q0 + ql) * 36 + off + d] = a;
        }
    }
}

template<int DK, int NQ, bool TWOPASS>
__device__ void attn_run(const float* ksh, const float* vsh, const float* qsh,
                         float* ob, float* sb, int q0, int lane, int wid)
{
    constexpr int H  = 36 / DK;
    constexpr int NG = (QT + NQ - 1) / NQ;
    for (int u = wid; u < H * NG; u += NWARP) {
        int hh = u / NG, g = u % NG;
        if (TWOPASS)
            attn_hg_2pass<DK, NQ>(ksh, vsh, qsh, ob, sb, q0, g, hh * DK, lane);
        else
            attn_hg_online<DK, NQ>(ksh, vsh, qsh, ob, sb, q0, g, hh * DK, lane);
    }
}

__global__ void __launch_bounds__(320, 2) attn_kernel(int4 heads4)
{
    extern __shared__ float sh[];
    float* ksh = sh;
    float* vsh = sh + KH * KVP;
    float* qsh = sh + 2 * KH * KVP;
    int tile = blockIdx.x >> 1, half = blockIdx.x & 1;
    int b = blockIdx.y, s = blockIdx.z;
    int h = pick4(heads4, s);
    int base = (s * 4 + b) * 21600;
    int kbase = base + half * KH * 36;

    const float4* kg = (const float4*)(g_k + kbase);
    const float4* vg = (const float4*)(g_v + kbase);
    for (int i4 = threadIdx.x; i4 < KH * 9; i4 += 320) {
        int row = i4 / 9, c = (i4 % 9) * 4;
        float4 kv = kg[i4], vv = vg[i4];
        float* kd = ksh + row * KVP + c;
        kd[0] = kv.x; kd[1] = kv.y; kd[2] = kv.z; kd[3] = kv.w;
        float* vd = vsh + row * KVP + c;
        vd[0] = vv.x; vd[1] = vv.y; vd[2] = vv.z; vd[3] = vv.w;
    }
    int q0 = tile * QT;
    for (int i = threadIdx.x; i < QT * 36; i += 320) qsh[i] = g_q[base + q0 * 36 + i];
    __syncthreads();

    int lane = threadIdx.x & 31, wid = threadIdx.x >> 5;
    float* ob = (half ? g_o1 : g_o0) + base;
    float* sb = (half ? g_s1 : g_s0) + base;
    switch (h) {
        case 1:  attn_run<36, 2, true >(ksh, vsh, qsh, ob, sb, q0, lane, wid); break;
        case 2:  attn_run<18, 3, true >(ksh, vsh, qsh, ob, sb, q0, lane, wid); break;
        case 3:  attn_run<12, 3, true >(ksh, vsh, qsh, ob, sb, q0, lane, wid); break;
        case 4:  attn_run<9,  4, false>(ksh, vsh, qsh, ob, sb, q0, lane, wid); break;
        case 6:  attn_run<6,  6, false>(ksh, vsh, qsh, ob, sb, q0, lane, wid); break;
        case 9:  attn_run<4,  8, false>(ksh, vsh, qsh, ob, sb, q0, lane, wid); break;
        case 12: attn_run<3, 10, false>(ksh, vsh, qsh, ob, sb, q0, lane, wid); break;
        case 18: attn_run<2, 15, false>(ksh, vsh, qsh, ob, sb, q0, lane, wid); break;
        case 36: attn_run<1, 15, false>(ksh, vsh, qsh, ob, sb, q0, lane, wid); break;
    }
}

// ---------------- SE gate ----------------
__global__ void __launch_bounds__(288) gate_kernel()
{
    int sb = blockIdx.x;
    __shared__ float red[288];
    int t = threadIdx.x;
    int c = t / 8, k = t % 8;
    float sum = 0.f;
    const float* zz = g_z + sb * 21600;
    for (int l = k; l < 600; l += 8) sum += zz[l * 36 + c];
    red[t] = sum;
    __syncthreads();
    if (k == 0) {
        float tot = 0.f;
#pragma unroll
        for (int i = 0; i < 8; i++) tot += red[c * 8 + i];
        float mean = tot * (1.f / 600.f);
        g_gate[sb * 36 + c] = 1.f / (1.f + __expf(-mean));
    }
}

// ---------------- conv + BN + ReLU ----------------
__global__ void __launch_bounds__(360) conv_kernel(
    const float* __restrict__ conv_w, const float* __restrict__ conv_b,
    const float* __restrict__ bn_g, const float* __restrict__ bn_b,
    const float* __restrict__ bn_mean, const float* __restrict__ bn_var,
    float* __restrict__ out)
{
    extern __shared__ float esh[];
    float* xf  = esh;
    float* wsh = esh + 144 * 32;
    int b = blockIdx.y, lbase = blockIdx.x * 30;
    int t = threadIdx.x;

    for (int idx = t; idx < 144 * 32; idx += 360) {
        int i = idx >> 5, lc = idx & 31;
        int l = lbase + lc - 1;
        float val = 0.f;
        if (l >= 0 && l < 600) {
            int s = i / 36, c = i % 36;
            val = g_gate[(s * 4 + b) * 36 + c] * g_z[((s * 4 + b) * 600 + l) * 36 + c];
        }
        xf[i * 32 + lc] = val;
    }
    for (int idx = t; idx < 36 * 432; idx += 360) {
        int o = idx / 432, rest = idx % 432;
        wsh[o * 433 + rest] = conv_w[idx];
    }
    __syncthreads();

    int o = t % 36, lj = t / 36;
    float scale = bn_g[o] * rsqrtf(bn_var[o] + 1e-5f);
    float shift = bn_b[o] - scale * bn_mean[o];
    float cb = conv_b[o];
    const float* w = wsh + o * 433;
#pragma unroll
    for (int rep = 0; rep < 3; rep++) {
        int lc = lj + rep * 10;
        float acc = cb;
#pragma unroll 8
        for (int i = 0; i < 144; i++) {
            float x0 = xf[i * 32 + lc];
            float x1 = xf[i * 32 + lc + 1];
            float x2 = xf[i * 32 + lc + 2];
            acc += x0 * w[i * 3 + 0] + x1 * w[i * 3 + 1] + x2 * w[i * 3 + 2];
        }
        float y = scale * acc + shift;
        out[b * 21600 + o * 600 + lbase + lc] = fmaxf(y, 0.f);
    }
}

// ---------------- host driver ----------------
extern "C" void kernel_launch(void* const* d_in, const int* in_sizes, int n_in,
                              void* d_out, int out_size)
{
    (void)in_sizes; (void)n_in; (void)out_size;
    const float* x     = (const float*)d_in[0];
    const float* ln1_g = (const float*)d_in[1];
    const float* ln1_b = (const float*)d_in[2];
    const float* Wq    = (const float*)d_in[3];
    const float* bq    = (const float*)d_in[4];
    const float* Wk    = (const float*)d_in[5];
    const float* bk    = (const float*)d_in[6];
    const float* Wv    = (const float*)d_in[7];
    const float* bv    = (const float*)d_in[8];
    const float* Wo    = (const float*)d_in[9];
    const float* bo    = (const float*)d_in[10];
    const float* ln2_g = (const float*)d_in[11];
    const float* ln2_b = (const float*)d_in[12];
    const float* W1    = (const float*)d_in[13];
    const float* b1    = (const float*)d_in[14];
    const float* W2    = (const float*)d_in[15];
    const float* b2    = (const float*)d_in[16];
    const float* conv_w = (const float*)d_in[17];
    const float* conv_b = (const float*)d_in[18];
    const float* bn_g   = (const float*)d_in[19];
    const float* bn_b   = (const float*)d_in[20];
    const float* bn_mean = (const float*)d_in[21];
    const float* bn_var  = (const float*)d_in[22];
    float* out = (float*)d_out;

    static const int HEADS_H[24] = {1,2,3,4,6,9,12,18,36,
                                    1,2,3,4,6,
                                    6,9,12,18,36,
                                    3,4,6,9,12};
    static const int START[4] = {0, 9, 14, 19};
    static const int DEPTH[4] = {9, 5, 5, 5};

    const int ATTN_SMEM = (2 * KH * KVP + QT * 36) * 4;   // 93,120 B
    const int CONV_SMEM = (144 * 32 + 36 * 433) * 4;
    const int RC_SMEM   = RC_TOT * 4;
    const int LQ_SMEM   = LQ_TOT * 4;
    cudaFuncSetAttribute(attn_kernel, cudaFuncAttributeMaxDynamicSharedMemorySize, ATTN_SMEM);
    cudaFuncSetAttribute(conv_kernel, cudaFuncAttributeMaxDynamicSharedMemorySize, CONV_SMEM);
    cudaFuncSetAttribute(rowchain_kernel, cudaFuncAttributeMaxDynamicSharedMemorySize, RC_SMEM);
    cudaFuncSetAttribute(lnqkv2_kernel, cudaFuncAttributeMaxDynamicSharedMemorySize, LQ_SMEM);

    int4 L0 = make_int4(0, 9, 14, 19);
    lnqkv2_kernel<<<dim3(75, 1, 4), 512, LQ_SMEM>>>(L0, x, ln1_g, ln1_b,
                                                    Wq, bq, Wk, bk, Wv, bv);

    for (int t = 0; t < 9; t++) {
        int nA = (t < 5) ? 4 : 1;
        int lc[4], nx[4], hh[4];
        for (int s = 0; s < 4; s++) {
            int L = START[s] + t;
            lc[s] = (L < 24) ? L : 0;
            hh[s] = (t < DEPTH[s]) ? HEADS_H[lc[s]] : 1;
            nx[s] = (t + 1 < DEPTH[s]) ? lc[s] + 1 : -1;
        }
        int4 Lc = make_int4(lc[0], lc[1], lc[2], lc[3]);
        int4 Nx = make_int4(nx[0], nx[1], nx[2], nx[3]);
        int4 Hh = make_int4(hh[0], hh[1], hh[2], hh[3]);
        int4 Dk = make_int4(36 / hh[0], 36 / hh[1], 36 / hh[2], 36 / hh[3]);

        attn_kernel<<<dim3(NTILES * 2, 4, nA), 320, ATTN_SMEM>>>(Hh);
        rowchain_kernel<<<dim3(75, 1, nA), 512, RC_SMEM>>>(
            Lc, Nx, Dk, Wo, bo, ln2_g, ln2_b, W1, b1, W2, b2,
            ln1_g, ln1_b, Wq, bq, Wk, bk, Wv, bv);
    }

    gate_kernel<<<16, 288>>>();
    conv_kernel<<<dim3(20, 4), 360, CONV_SMEM>>>(conv_w, conv_b, bn_g, bn_b,
                                                 bn_mean, bn_var, out);
}